// round 11
// baseline (speedup 1.0000x reference)
#include <cuda_runtime.h>
#include <cuda_bf16.h>
#include <cstdint>
#include <math.h>

// Problem constants
#define D_MODEL 1024
#define NHEADS  16
#define DHEAD   64
#define BATCH   4
#define SEQ     2048
#define MROWS   (BATCH * SEQ)   // 8192

// ---------------------------------------------------------------------------
// Scratch (__device__ globals; no cudaMalloc allowed)
// ---------------------------------------------------------------------------
__device__ float g_q[MROWS * D_MODEL];
__device__ float g_k[MROWS * D_MODEL];
__device__ float g_v[MROWS * D_MODEL];
__device__ float g_xt[MROWS * D_MODEL];                 // x tf32-rounded
__device__ float g_wt[2][D_MODEL * D_MODEL];            // Wq^T, Wk^T tf32-rounded
__device__ __nv_bfloat16 g_xh[MROWS * D_MODEL];
__device__ __nv_bfloat16 g_xl[MROWS * D_MODEL];
__device__ __nv_bfloat16 g_ah[MROWS * D_MODEL];
__device__ __nv_bfloat16 g_al[MROWS * D_MODEL];
__device__ __nv_bfloat16 g_wh[4][D_MODEL * D_MODEL];   // W^T hi (slots 2,3 used)
__device__ __nv_bfloat16 g_wl[4][D_MODEL * D_MODEL];   // W^T lo (slots 2,3 used)

// ---------------------------------------------------------------------------
// PTX helpers (compute_103-safe)
// ---------------------------------------------------------------------------
__device__ __forceinline__ uint32_t smem_u32(const void* p) {
    uint32_t a;
    asm("{ .reg .u64 t; cvta.to.shared.u64 t, %1; cvt.u32.u64 %0, t; }" : "=r"(a) : "l"(p));
    return a;
}
__device__ __forceinline__ void cp16(uint32_t s, const void* g) {
    asm volatile("cp.async.cg.shared.global [%0], [%1], 16;" :: "r"(s), "l"(g));
}
__device__ __forceinline__ void ldsm4(uint32_t* r, uint32_t a) {
    asm volatile("ldmatrix.sync.aligned.m8n8.x4.shared.b16 {%0,%1,%2,%3}, [%4];"
                 : "=r"(r[0]), "=r"(r[1]), "=r"(r[2]), "=r"(r[3]) : "r"(a));
}
__device__ __forceinline__ void mma16816(float* d, const uint32_t* a, const uint32_t* b) {
    asm volatile(
        "mma.sync.aligned.m16n8k16.row.col.f32.bf16.bf16.f32 "
        "{%0,%1,%2,%3}, {%4,%5,%6,%7}, {%8,%9}, {%0,%1,%2,%3};"
        : "+f"(d[0]), "+f"(d[1]), "+f"(d[2]), "+f"(d[3])
        : "r"(a[0]), "r"(a[1]), "r"(a[2]), "r"(a[3]), "r"(b[0]), "r"(b[1]));
}
__device__ __forceinline__ void mma1688_tf32(float* d, const uint32_t* a, uint32_t b0, uint32_t b1) {
    asm volatile(
        "mma.sync.aligned.m16n8k8.row.col.f32.tf32.tf32.f32 "
        "{%0,%1,%2,%3}, {%4,%5,%6,%7}, {%8,%9}, {%0,%1,%2,%3};"
        : "+f"(d[0]), "+f"(d[1]), "+f"(d[2]), "+f"(d[3])
        : "r"(a[0]), "r"(a[1]), "r"(a[2]), "r"(a[3]), "r"(b0), "r"(b1));
}
__device__ __forceinline__ uint32_t f2tf32(float v) {
    uint32_t u;
    asm("cvt.rna.tf32.f32 %0, %1;" : "=r"(u) : "f"(v));
    return u;
}

// ---------------------------------------------------------------------------
// fp32 -> (hi, lo) bf16 split + tf32-rounded copy
// ---------------------------------------------------------------------------
__global__ __launch_bounds__(256)
void split_kernel(const float* __restrict__ in,
                  __nv_bfloat16* __restrict__ hi,
                  __nv_bfloat16* __restrict__ lo,
                  float* __restrict__ tf, int n4)
{
    int i = blockIdx.x * blockDim.x + threadIdx.x;
    if (i >= n4) return;
    float4 v = ((const float4*)in)[i];
    __nv_bfloat16 h0 = __float2bfloat16(v.x);
    __nv_bfloat16 h1 = __float2bfloat16(v.y);
    __nv_bfloat16 h2 = __float2bfloat16(v.z);
    __nv_bfloat16 h3 = __float2bfloat16(v.w);
    __nv_bfloat16 l0 = __float2bfloat16(v.x - __bfloat162float(h0));
    __nv_bfloat16 l1 = __float2bfloat16(v.y - __bfloat162float(h1));
    __nv_bfloat16 l2 = __float2bfloat16(v.z - __bfloat162float(h2));
    __nv_bfloat16 l3 = __float2bfloat16(v.w - __bfloat162float(h3));
    ((__nv_bfloat162*)hi)[2 * i]     = __nv_bfloat162(h0, h1);
    ((__nv_bfloat162*)hi)[2 * i + 1] = __nv_bfloat162(h2, h3);
    ((__nv_bfloat162*)lo)[2 * i]     = __nv_bfloat162(l0, l1);
    ((__nv_bfloat162*)lo)[2 * i + 1] = __nv_bfloat162(l2, l3);
    uint4 t;
    t.x = f2tf32(v.x); t.y = f2tf32(v.y); t.z = f2tf32(v.z); t.w = f2tf32(v.w);
    ((uint4*)tf)[i] = t;
}

// ---------------------------------------------------------------------------
// W [K,N] fp32 -> W^T [N,K]; wsel 0,1 -> tf32 fp32; wsel 2,3 -> bf16 hi/lo
// ---------------------------------------------------------------------------
__global__ __launch_bounds__(256)
void wsplit_kernel(const float* __restrict__ W0, const float* __restrict__ W1,
                   const float* __restrict__ W2, const float* __restrict__ W3,
                   float* __restrict__ wt_base,
                   __nv_bfloat16* __restrict__ th_base,
                   __nv_bfloat16* __restrict__ tl_base)
{
    __shared__ float t[32][33];
    const int wsel = blockIdx.z;
    const float* W = (wsel == 0) ? W0 : (wsel == 1) ? W1 : (wsel == 2) ? W2 : W3;
    const int bx = blockIdx.x * 32;   // col block (N)
    const int by = blockIdx.y * 32;   // row block (K)
    const int x = threadIdx.x, y = threadIdx.y;   // 32 x 8
#pragma unroll
    for (int i = 0; i < 32; i += 8)
        t[y + i][x] = W[(size_t)(by + y + i) * D_MODEL + bx + x];
    __syncthreads();
    if (wsel < 2) {
        float* wt = wt_base + (size_t)wsel * D_MODEL * D_MODEL;
#pragma unroll
        for (int i = 0; i < 32; i += 8) {
            float v = t[x][y + i];
            size_t o = (size_t)(bx + y + i) * D_MODEL + by + x;
            wt[o] = __uint_as_float(f2tf32(v));
        }
    } else {
        __nv_bfloat16* th = th_base + (size_t)wsel * D_MODEL * D_MODEL;
        __nv_bfloat16* tl = tl_base + (size_t)wsel * D_MODEL * D_MODEL;
#pragma unroll
        for (int i = 0; i < 32; i += 8) {
            float v = t[x][y + i];
            size_t o = (size_t)(bx + y + i) * D_MODEL + by + x;
            __nv_bfloat16 h = __float2bfloat16(v);
            th[o] = h;
            tl[o] = __float2bfloat16(v - __bfloat162float(h));
        }
    }
}

// ---------------------------------------------------------------------------
// bf16 split-3-term GEMM (V and O projections), 128x64 tile, 2 CTAs/SM.
// 8 warps 4x2, warp tile 32x32, cp.async double buffer, stride-72 smem.
// ---------------------------------------------------------------------------
#define BM 128
#define BN 64
#define BK 64
#define NCHUNK (D_MODEL / BK)          // 16
#define LDSTRIDE 72
#define AMAT (BM * LDSTRIDE * 2)       // 18432
#define BMAT (BN * LDSTRIDE * 2)       // 9216
#define STAGE_BYTES (2 * AMAT + 2 * BMAT)   // 55296
#define GEMM_SMEM (2 * STAGE_BYTES)         // 110592

__global__ __launch_bounds__(256, 2)
void gemm_o_kernel(const __nv_bfloat16* __restrict__ Ah,
                   const __nv_bfloat16* __restrict__ Al,
                   const __nv_bfloat16* __restrict__ Bh,
                   const __nv_bfloat16* __restrict__ Bl,
                   const float* __restrict__ bias,
                   float* __restrict__ C)
{
    extern __shared__ __align__(128) char smem[];
    const uint32_t sb = smem_u32(smem);
    const int tid  = threadIdx.x;
    const int wid  = tid >> 5;
    const int lane = tid & 31;
    const int wm = wid >> 1;          // 0..3 (32 rows each)
    const int wn = wid & 1;           // 0..1 (32 cols each)
    const int rowA0 = blockIdx.y * BM;
    const int rowB0 = blockIdx.x * BN;

    // loader: A 1024 chunks (hi+lo), B 512 chunks (hi+lo) -> 12 cp16/thread
    auto issue = [&](int c, int s) {
        const uint32_t sbase = sb + (uint32_t)s * STAGE_BYTES;
#pragma unroll
        for (int i = 0; i < 4; ++i) {
            int cid = tid + i * 256;          // 0..1023
            int row = cid >> 3;
            int kc  = cid & 7;
            uint32_t so = (uint32_t)(row * LDSTRIDE + kc * 8) * 2;
            size_t ga = (size_t)(rowA0 + row) * D_MODEL + c * BK + kc * 8;
            cp16(sbase + so, Ah + ga);
            cp16(sbase + AMAT + so, Al + ga);
        }
#pragma unroll
        for (int i = 0; i < 2; ++i) {
            int cid = tid + i * 256;          // 0..511
            int row = cid >> 3;
            int kc  = cid & 7;
            uint32_t so = (uint32_t)(row * LDSTRIDE + kc * 8) * 2;
            size_t gb = (size_t)(rowB0 + row) * D_MODEL + c * BK + kc * 8;
            cp16(sbase + 2 * AMAT + so, Bh + gb);
            cp16(sbase + 2 * AMAT + BMAT + so, Bl + gb);
        }
        asm volatile("cp.async.commit_group;" ::: "memory");
    };

    float acc[2][4][4];
#pragma unroll
    for (int mt = 0; mt < 2; ++mt)
#pragma unroll
        for (int nt = 0; nt < 4; ++nt)
#pragma unroll
            for (int i = 0; i < 4; ++i)
                acc[mt][nt][i] = 0.0f;

    const int arow = lane & 15;
    const int acol = (lane >> 4) * 8;
    const int brow = (lane & 7) + ((lane >> 4) << 3);
    const int bcol = ((lane >> 3) & 1) * 8;

    issue(0, 0);

    for (int c = 0; c < NCHUNK; ++c) {
        if (c + 1 < NCHUNK) {
            issue(c + 1, (c + 1) & 1);
            asm volatile("cp.async.wait_group 1;" ::: "memory");
        } else {
            asm volatile("cp.async.wait_group 0;" ::: "memory");
        }
        __syncthreads();

        const uint32_t sbase = sb + (uint32_t)(c & 1) * STAGE_BYTES;
        const uint32_t aH = sbase;
        const uint32_t aL = sbase + AMAT;
        const uint32_t bH = sbase + 2 * AMAT;
        const uint32_t bL = sbase + 2 * AMAT + BMAT;

#pragma unroll
        for (int ks = 0; ks < 4; ++ks) {
            const int k0 = ks * 16;
            uint32_t ah[2][4], al[2][4];
#pragma unroll
            for (int mt = 0; mt < 2; ++mt) {
                uint32_t off = (uint32_t)((wm * 32 + mt * 16 + arow) * LDSTRIDE + k0 + acol) * 2;
                ldsm4(ah[mt], aH + off);
                ldsm4(al[mt], aL + off);
            }
            uint32_t bh[2][4], bl[2][4];
#pragma unroll
            for (int bt = 0; bt < 2; ++bt) {
                uint32_t off = (uint32_t)((wn * 32 + bt * 16 + brow) * LDSTRIDE + k0 + bcol) * 2;
                ldsm4(bh[bt], bH + off);
                ldsm4(bl[bt], bL + off);
            }
#pragma unroll
            for (int mt = 0; mt < 2; ++mt)
#pragma unroll
                for (int nt = 0; nt < 4; ++nt) {
                    const uint32_t* B_h = &bh[nt >> 1][(nt & 1) * 2];
                    const uint32_t* B_l = &bl[nt >> 1][(nt & 1) * 2];
                    mma16816(acc[mt][nt], ah[mt], B_h);
                    mma16816(acc[mt][nt], ah[mt], B_l);
                    mma16816(acc[mt][nt], al[mt], B_h);
                }
        }
        __syncthreads();
    }

    const int qr = lane >> 2;
    const int qc = (lane & 3) * 2;
#pragma unroll
    for (int mt = 0; mt < 2; ++mt) {
        const int r0 = rowA0 + wm * 32 + mt * 16 + qr;
#pragma unroll
        for (int nt = 0; nt < 4; ++nt) {
            const int col = rowB0 + wn * 32 + nt * 8 + qc;
            const float b0 = bias[col];
            const float b1 = bias[col + 1];
            float2 v0, v1;
            v0.x = acc[mt][nt][0] + b0;  v0.y = acc[mt][nt][1] + b1;
            v1.x = acc[mt][nt][2] + b0;  v1.y = acc[mt][nt][3] + b1;
            *(float2*)&C[(size_t)r0 * D_MODEL + col]       = v0;
            *(float2*)&C[(size_t)(r0 + 8) * D_MODEL + col] = v1;
        }
    }
}

// ---------------------------------------------------------------------------
// tf32 1-term GEMM (Q and K projections), 128x64 tile, 2 CTAs/SM.
// 8 warps 4x2, warp tile 32x32, m16n8k8 tf32, stride-68 smem.
// ---------------------------------------------------------------------------
#define TSTR 68
#define TAMAT (128 * TSTR * 4)          // 34816
#define TBMAT (64 * TSTR * 4)           // 17408
#define TSTAGE (TAMAT + TBMAT)          // 52224
#define TGEMM_SMEM (2 * TSTAGE)         // 104448

__global__ __launch_bounds__(256, 2)
void gemm_qk_tf32(const float* __restrict__ A,
                  const float* __restrict__ Wt0,
                  const float* __restrict__ bq, const float* __restrict__ bk,
                  float* __restrict__ qb, float* __restrict__ kb)
{
    extern __shared__ __align__(128) char smem[];
    const uint32_t sb = smem_u32(smem);
    const int tid  = threadIdx.x;
    const int wid  = tid >> 5;
    const int lane = tid & 31;
    const int wm = wid >> 1;          // 0..3
    const int wn = wid & 1;           // 0..1

    const int which = blockIdx.x >> 4;            // 0 = Q, 1 = K
    const int rowB0 = (blockIdx.x & 15) * BN;
    const int rowA0 = blockIdx.y * BM;
    const float* Wt = Wt0 + (size_t)which * D_MODEL * D_MODEL;
    const float* bias = which ? bk : bq;
    float* C = which ? kb : qb;

    // loader: A 2048 chunks, B 1024 chunks -> 12 cp16/thread
    auto issue = [&](int c, int s) {
        const uint32_t sbase = sb + (uint32_t)s * TSTAGE;
#pragma unroll
        for (int i = 0; i < 8; ++i) {
            int cid = tid + i * 256;             // 0..2047
            int row = cid >> 4;
            int kc  = cid & 15;
            uint32_t so = (uint32_t)(row * TSTR + kc * 4) * 4;
            size_t ga = (size_t)(rowA0 + row) * D_MODEL + c * BK + kc * 4;
            cp16(sbase + so, A + ga);
        }
#pragma unroll
        for (int i = 0; i < 4; ++i) {
            int cid = tid + i * 256;             // 0..1023
            int row = cid >> 4;
            int kc  = cid & 15;
            uint32_t so = (uint32_t)(row * TSTR + kc * 4) * 4;
            size_t gb = (size_t)(rowB0 + row) * D_MODEL + c * BK + kc * 4;
            cp16(sbase + TAMAT + so, Wt + gb);
        }
        asm volatile("cp.async.commit_group;" ::: "memory");
    };

    float acc[2][4][4];
#pragma unroll
    for (int mt = 0; mt < 2; ++mt)
#pragma unroll
        for (int nt = 0; nt < 4; ++nt)
#pragma unroll
            for (int i = 0; i < 4; ++i)
                acc[mt][nt][i] = 0.0f;

    const int lmat = lane >> 3;
    const int lrow = lane & 7;
    const int rofs = (lmat & 1) * 8 + lrow;
    const int cofs = (lmat >> 1) * 4;

    issue(0, 0);

    for (int c = 0; c < NCHUNK; ++c) {
        if (c + 1 < NCHUNK) {
            issue(c + 1, (c + 1) & 1);
            asm volatile("cp.async.wait_group 1;" ::: "memory");
        } else {
            asm volatile("cp.async.wait_group 0;" ::: "memory");
        }
        __syncthreads();

        const uint32_t aB = sb + (uint32_t)(c & 1) * TSTAGE;
        const uint32_t bB = aB + TAMAT;

#pragma unroll
        for (int ks = 0; ks < 8; ++ks) {
            const int k0f = ks * 8;
            uint32_t ar[2][4];
#pragma unroll
            for (int mt = 0; mt < 2; ++mt) {
                uint32_t off = (uint32_t)((wm * 32 + mt * 16 + rofs) * TSTR + k0f + cofs) * 4;
                ldsm4(ar[mt], aB + off);
            }
            uint32_t br[2][4];
#pragma unroll
            for (int np = 0; np < 2; ++np) {
                uint32_t off = (uint32_t)((wn * 32 + np * 16 + rofs) * TSTR + k0f + cofs) * 4;
                ldsm4(br[np], bB + off);
            }
#pragma unroll
            for (int mt = 0; mt < 2; ++mt)
#pragma unroll
                for (int nt = 0; nt < 4; ++nt)
                    mma1688_tf32(acc[mt][nt], ar[mt],
                                 br[nt >> 1][nt & 1], br[nt >> 1][2 + (nt & 1)]);
        }
        __syncthreads();
    }

    const int qr = lane >> 2;
    const int qc = (lane & 3) * 2;
#pragma unroll
    for (int mt = 0; mt < 2; ++mt) {
        const int r0 = rowA0 + wm * 32 + mt * 16 + qr;
#pragma unroll
        for (int nt = 0; nt < 4; ++nt) {
            const int col = rowB0 + wn * 32 + nt * 8 + qc;
            const float b0 = bias[col];
            const float b1 = bias[col + 1];
            float2 v0, v1;
            v0.x = acc[mt][nt][0] + b0;  v0.y = acc[mt][nt][1] + b1;
            v1.x = acc[mt][nt][2] + b0;  v1.y = acc[mt][nt][3] + b1;
            *(float2*)&C[(size_t)r0 * D_MODEL + col]       = v0;
            *(float2*)&C[(size_t)(r0 + 8) * D_MODEL + col] = v1;
        }
    }
}

// ---------------------------------------------------------------------------
// Dilated attention v2 (unchanged from R8): lane = neighbor / lane = dim.
// ---------------------------------------------------------------------------
#define QTILE 32
#define CAP_ROWS 80
#define ASTR 68
#define ATT_SMEM ((2 * CAP_ROWS + QTILE) * ASTR * 4 + 8 * 32 * 4)

__global__ __launch_bounds__(256)
void attn_tile_kernel(const float* __restrict__ Q,
                      const float* __restrict__ Kb,
                      const float* __restrict__ V,
                      __nv_bfloat16* __restrict__ Oh,
                      __nv_bfloat16* __restrict__ Ol,
                      const int* __restrict__ kptr,
                      const int* __restrict__ dptr)
{
    extern __shared__ __align__(16) float sm[];
    float* Ks = sm;
    float* Vs = Ks + CAP_ROWS * ASTR;
    float* Qs = Vs + CAP_ROWS * ASTR;
    float* Ps = Qs + QTILE * ASTR;

    const int tid  = threadIdx.x;
    const int wid  = tid >> 5;
    const int lane = tid & 31;

    const int qt = blockIdx.x & (SEQ / QTILE - 1);
    const int bh = blockIdx.x / (SEQ / QTILE);
    const int h  = bh % NHEADS;
    const int b  = bh / NHEADS;
    const int q0 = qt * QTILE;

    const int kw   = *kptr;
    const int dil  = *dptr;
    const int koff = kw * dil;
    const int tmax = 2 * kw;

    const int base = max(0, q0 - koff);
    const int top  = min(SEQ - 1, q0 + QTILE - 1 + koff);
    const int rows = top - base + 1;
    const bool fast = (rows <= CAP_ROWS) && (tmax <= 31);

    const size_t gbase = (size_t)(b * SEQ) * D_MODEL + h * DHEAD;
    const float scale = rsqrtf((float)DHEAD);

    if (fast) {
        const int nchunk = rows * (DHEAD / 4);
        for (int c = tid; c < nchunk; c += 256) {
            const int r = c >> 4, d4 = (c & 15);
            const size_t g = gbase + (size_t)(base + r) * D_MODEL + d4 * 4;
            *(float4*)&Ks[r * ASTR + d4 * 4] = *(const float4*)&Kb[g];
            *(float4*)&Vs[r * ASTR + d4 * 4] = *(const float4*)&V[g];
        }
        for (int c = tid; c < QTILE * (DHEAD / 4); c += 256) {
            const int r = c >> 4, d4 = (c & 15);
            *(float4*)&Qs[r * ASTR + d4 * 4] =
                *(const float4*)&Q[gbase + (size_t)(q0 + r) * D_MODEL + d4 * 4];
        }
        __syncthreads();

        float* Pw = Ps + wid * 32;

#pragma unroll
        for (int qi = 0; qi < 4; ++qi) {
            const int q = q0 + wid * 4 + qi;
            const int r0q = q - koff - base;

            const int t = lane;
            const int j = q + (t - kw) * dil;
            const bool act = (t <= tmax) && (j >= 0) && (j < SEQ);
            const int rj = min(max(r0q + t * dil, 0), rows - 1);

            float s = 0.0f;
            const float4* krow = (const float4*)&Ks[rj * ASTR];
            const float4* qrow = (const float4*)&Qs[(q - q0) * ASTR];
#pragma unroll
            for (int d4 = 0; d4 < 16; ++d4) {
                float4 kk = krow[d4];
                float4 qq = qrow[d4];
                s += qq.x * kk.x + qq.y * kk.y + qq.z * kk.z + qq.w * kk.w;
            }
            s = act ? s * scale : -1e30f;

            float mx = s;
#pragma unroll
            for (int o = 16; o > 0; o >>= 1)
                mx = fmaxf(mx, __shfl_xor_sync(0xffffffffu, mx, o));
            float e = act ? __expf(s - mx) : 0.0f;
            float sum = e;
#pragma unroll
            for (int o = 16; o > 0; o >>= 1)
                sum += __shfl_xor_sync(0xffffffffu, sum, o);

            Pw[lane] = e;
            __syncwarp();

            float a0 = 0.0f, a1 = 0.0f;
            int rj2 = r0q;
            for (int tt = 0; tt <= tmax; ++tt, rj2 += dil) {
                const float p = Pw[tt];
                const int r = min(max(rj2, 0), rows - 1);
                a0 += p * Vs[r * ASTR + lane];
                a1 += p * Vs[r * ASTR + lane + 32];
            }
            __syncwarp();

            const float inv = 1.0f / sum;
            const float o0 = a0 * inv, o1 = a1 * inv;
            const size_t rowq = gbase + (size_t)q * D_MODEL;
            __nv_bfloat16 h0 = __float2bfloat16(o0);
            __nv_bfloat16 h1 = __float2bfloat16(o1);
            Oh[rowq + lane]      = h0;
            Oh[rowq + lane + 32] = h1;
            Ol[rowq + lane]      = __float2bfloat16(o0 - __bfloat162float(h0));
            Ol[rowq + lane + 32] = __float2bfloat16(o1 - __bfloat162float(h1));
        }
        return;
    }

    // fallback: per-neighbor loop straight from gmem (general k/dil)
#pragma unroll
    for (int qi = 0; qi < 4; ++qi) {
        const int q = q0 + wid * 4 + qi;
        const size_t rowq = gbase + (size_t)q * D_MODEL;
        const float q0f = Q[rowq + lane];
        const float q1f = Q[rowq + lane + 32];

        float m = -1e30f, l = 0.0f, a0 = 0.0f, a1 = 0.0f;
        for (int t = 0; t <= tmax; ++t) {
            const int j = q + (t - kw) * dil;
            if (j < 0 || j >= SEQ) continue;
            const size_t rowj = gbase + (size_t)j * D_MODEL;
            float p = q0f * Kb[rowj + lane] + q1f * Kb[rowj + lane + 32];
#pragma unroll
            for (int s = 16; s > 0; s >>= 1)
                p += __shfl_xor_sync(0xffffffffu, p, s);
            const float sc = p * scale;
            const float mn   = fmaxf(m, sc);
            const float corr = __expf(m - mn);
            const float e    = __expf(sc - mn);
            a0 = a0 * corr + e * V[rowj + lane];
            a1 = a1 * corr + e * V[rowj + lane + 32];
            l  = l * corr + e;
            m  = mn;
        }
        const float inv = 1.0f / l;
        const float o0 = a0 * inv, o1 = a1 * inv;
        __nv_bfloat16 h0 = __float2bfloat16(o0);
        __nv_bfloat16 h1 = __float2bfloat16(o1);
        Oh[rowq + lane]      = h0;
        Oh[rowq + lane + 32] = h1;
        Ol[rowq + lane]      = __float2bfloat16(o0 - __bfloat162float(h0));
        Ol[rowq + lane + 32] = __float2bfloat16(o1 - __bfloat162float(h1));
    }
}

// ---------------------------------------------------------------------------
// Launch
// ---------------------------------------------------------------------------
extern "C" void kernel_launch(void* const* d_in, const int* in_sizes, int n_in,
                              void* d_out, int out_size)
{
    const float* x  = (const float*)d_in[0];
    const float* Wq = (const float*)d_in[1];
    const float* bq = (const float*)d_in[2];
    const float* Wk = (const float*)d_in[3];
    const float* bk = (const float*)d_in[4];
    const float* Wv = (const float*)d_in[5];
    const float* bv = (const float*)d_in[6];
    const float* Wo = (const float*)d_in[7];
    const float* bo = (const float*)d_in[8];
    const int*   kp = (const int*)d_in[9];
    const int*   dp = (const int*)d_in[10];
    float* out = (float*)d_out;

    void *pq, *pk, *pv, *pxt, *pwt, *pxh, *pxl, *pah, *pal, *pwh, *pwl;
    cudaGetSymbolAddress(&pq,  g_q);
    cudaGetSymbolAddress(&pk,  g_k);
    cudaGetSymbolAddress(&pv,  g_v);
    cudaGetSymbolAddress(&pxt, g_xt);
    cudaGetSymbolAddress(&pwt, g_wt);
    cudaGetSymbolAddress(&pxh, g_xh);
    cudaGetSymbolAddress(&pxl, g_xl);
    cudaGetSymbolAddress(&pah, g_ah);
    cudaGetSymbolAddress(&pal, g_al);
    cudaGetSymbolAddress(&pwh, g_wh);
    cudaGetSymbolAddress(&pwl, g_wl);
    float* qbuf = (float*)pq;
    float* kbuf = (float*)pk;
    float* vbuf = (float*)pv;
    float* xt   = (float*)pxt;
    float* wt   = (float*)pwt;
    __nv_bfloat16* xh = (__nv_bfloat16*)pxh;
    __nv_bfloat16* xl = (__nv_bfloat16*)pxl;
    __nv_bfloat16* ah = (__nv_bfloat16*)pah;
    __nv_bfloat16* al = (__nv_bfloat16*)pal;
    __nv_bfloat16* wh = (__nv_bfloat16*)pwh;
    __nv_bfloat16* wl = (__nv_bfloat16*)pwl;
    const size_t WSZ = (size_t)D_MODEL * D_MODEL;

    cudaFuncSetAttribute(gemm_o_kernel,  cudaFuncAttributeMaxDynamicSharedMemorySize, GEMM_SMEM);
    cudaFuncSetAttribute(gemm_qk_tf32,   cudaFuncAttributeMaxDynamicSharedMemorySize, TGEMM_SMEM);
    cudaFuncSetAttribute(attn_tile_kernel, cudaFuncAttributeMaxDynamicSharedMemorySize, ATT_SMEM);

    // 1) x -> bf16 hi/lo + tf32-rounded
    {
        int n4 = MROWS * D_MODEL / 4;
        split_kernel<<<(n4 + 255) / 256, 256>>>(x, xh, xl, xt, n4);
    }
    // 2) weights: Wq,Wk -> tf32 W^T; Wv,Wo -> bf16 hi/lo W^T
    {
        dim3 tb(32, 8), tg(D_MODEL / 32, D_MODEL / 32, 4);
        wsplit_kernel<<<tg, tb>>>(Wq, Wk, Wv, Wo, wt, wh, wl);
    }
    // 3) Q,K projections: tf32 1-term (2 outputs x 16 N-tiles)
    {
        dim3 gg(2 * (D_MODEL / BN), MROWS / BM);   // (32, 64)
        gemm_qk_tf32<<<gg, 256, TGEMM_SMEM>>>(xt, wt, bq, bk, qbuf, kbuf);
    }
    // 4) V projection: bf16 3-term
    {
        dim3 gg(D_MODEL / BN, MROWS / BM);         // (16, 64)
        gemm_o_kernel<<<gg, 256, GEMM_SMEM>>>(xh, xl, wh + 2 * WSZ, wl + 2 * WSZ, bv, vbuf);
    }
    // 5) dilated attention -> bf16 hi/lo
    {
        const int n_blocks = BATCH * NHEADS * (SEQ / QTILE);   // 4096
        attn_tile_kernel<<<n_blocks, 256, ATT_SMEM>>>(qbuf, kbuf, vbuf, ah, al, kp, dp);
    }
    // 6) output projection -> d_out
    {
        dim3 gg(D_MODEL / BN, MROWS / BM);
        gemm_o_kernel<<<gg, 256, GEMM_SMEM>>>(ah, al, wh + 3 * WSZ, wl + 3 * WSZ, bo, out);
    }
}

// round 12
// speedup vs baseline: 1.1325x; 1.1325x over previous
#include <cuda_runtime.h>
#include <cuda_bf16.h>
#include <cstdint>
#include <math.h>

// Problem constants
#define D_MODEL 1024
#define NHEADS  16
#define DHEAD   64
#define BATCH   4
#define SEQ     2048
#define MROWS   (BATCH * SEQ)   // 8192

// ---------------------------------------------------------------------------
// Scratch (__device__ globals; no cudaMalloc allowed)
// ---------------------------------------------------------------------------
__device__ float g_q[MROWS * D_MODEL];
__device__ float g_k[MROWS * D_MODEL];
__device__ float g_v[MROWS * D_MODEL];
__device__ float g_xt[MROWS * D_MODEL];        // x tf32-rounded
__device__ float g_at[MROWS * D_MODEL];        // attention out, tf32-rounded
__device__ float g_wt[4][D_MODEL * D_MODEL];   // Wq,Wk,Wv,Wo ^T tf32-rounded

// ---------------------------------------------------------------------------
// PTX helpers (compute_103-safe)
// ---------------------------------------------------------------------------
__device__ __forceinline__ uint32_t smem_u32(const void* p) {
    uint32_t a;
    asm("{ .reg .u64 t; cvta.to.shared.u64 t, %1; cvt.u32.u64 %0, t; }" : "=r"(a) : "l"(p));
    return a;
}
__device__ __forceinline__ void cp16(uint32_t s, const void* g) {
    asm volatile("cp.async.cg.shared.global [%0], [%1], 16;" :: "r"(s), "l"(g));
}
__device__ __forceinline__ void ldsm4(uint32_t* r, uint32_t a) {
    asm volatile("ldmatrix.sync.aligned.m8n8.x4.shared.b16 {%0,%1,%2,%3}, [%4];"
                 : "=r"(r[0]), "=r"(r[1]), "=r"(r[2]), "=r"(r[3]) : "r"(a));
}
__device__ __forceinline__ void mma1688_tf32(float* d, const uint32_t* a, uint32_t b0, uint32_t b1) {
    asm volatile(
        "mma.sync.aligned.m16n8k8.row.col.f32.tf32.tf32.f32 "
        "{%0,%1,%2,%3}, {%4,%5,%6,%7}, {%8,%9}, {%0,%1,%2,%3};"
        : "+f"(d[0]), "+f"(d[1]), "+f"(d[2]), "+f"(d[3])
        : "r"(a[0]), "r"(a[1]), "r"(a[2]), "r"(a[3]), "r"(b0), "r"(b1));
}
__device__ __forceinline__ uint32_t f2tf32(float v) {
    uint32_t u;
    asm("cvt.rna.tf32.f32 %0, %1;" : "=r"(u) : "f"(v));
    return u;
}

// ---------------------------------------------------------------------------
// fp32 -> tf32-rounded fp32, 4 elements/thread
// ---------------------------------------------------------------------------
__global__ __launch_bounds__(256)
void split_kernel(const float* __restrict__ in, float* __restrict__ tf, int n4)
{
    int i = blockIdx.x * blockDim.x + threadIdx.x;
    if (i >= n4) return;
    float4 v = ((const float4*)in)[i];
    uint4 t;
    t.x = f2tf32(v.x); t.y = f2tf32(v.y); t.z = f2tf32(v.z); t.w = f2tf32(v.w);
    ((uint4*)tf)[i] = t;
}

// ---------------------------------------------------------------------------
// W [K,N] fp32 -> W^T [N,K] tf32-rounded; blockIdx.z selects weight
// ---------------------------------------------------------------------------
__global__ __launch_bounds__(256)
void wsplit_kernel(const float* __restrict__ W0, const float* __restrict__ W1,
                   const float* __restrict__ W2, const float* __restrict__ W3,
                   float* __restrict__ wt_base)
{
    __shared__ float t[32][33];
    const int wsel = blockIdx.z;
    const float* W = (wsel == 0) ? W0 : (wsel == 1) ? W1 : (wsel == 2) ? W2 : W3;
    float* wt = wt_base + (size_t)wsel * D_MODEL * D_MODEL;
    const int bx = blockIdx.x * 32;   // col block (N)
    const int by = blockIdx.y * 32;   // row block (K)
    const int x = threadIdx.x, y = threadIdx.y;   // 32 x 8
#pragma unroll
    for (int i = 0; i < 32; i += 8)
        t[y + i][x] = W[(size_t)(by + y + i) * D_MODEL + bx + x];
    __syncthreads();
#pragma unroll
    for (int i = 0; i < 32; i += 8) {
        float v = t[x][y + i];
        size_t o = (size_t)(bx + y + i) * D_MODEL + by + x;
        wt[o] = __uint_as_float(f2tf32(v));
    }
}

// ---------------------------------------------------------------------------
// tf32 1-term GEMM core: C = A[M,K] @ Wt[N,K]^T + bias
// Tile 128x64x64, 256 thr (8 warps 4x2), warp tile 32x32, m16n8k8.
// cp.async double buffer, stride-68-float smem (conflict-free ldmatrix).
// ---------------------------------------------------------------------------
#define BM 128
#define BN 64
#define BK 64
#define NCHUNK (D_MODEL / BK)           // 16
#define TSTR 68
#define TAMAT (128 * TSTR * 4)          // 34816
#define TBMAT (64 * TSTR * 4)           // 17408
#define TSTAGE (TAMAT + TBMAT)          // 52224
#define TGEMM_SMEM (2 * TSTAGE)         // 104448

__device__ __forceinline__
void gemm_tf32_body(const float* __restrict__ A,
                    const float* __restrict__ Wt,
                    const float* __restrict__ bias,
                    float* __restrict__ C,
                    int rowA0, int rowB0, char* smem)
{
    const uint32_t sb = smem_u32(smem);
    const int tid  = threadIdx.x;
    const int wid  = tid >> 5;
    const int lane = tid & 31;
    const int wm = wid >> 1;          // 0..3
    const int wn = wid & 1;           // 0..1

    auto issue = [&](int c, int s) {
        const uint32_t sbase = sb + (uint32_t)s * TSTAGE;
#pragma unroll
        for (int i = 0; i < 8; ++i) {
            int cid = tid + i * 256;             // 0..2047
            int row = cid >> 4;
            int kc  = cid & 15;
            uint32_t so = (uint32_t)(row * TSTR + kc * 4) * 4;
            size_t ga = (size_t)(rowA0 + row) * D_MODEL + c * BK + kc * 4;
            cp16(sbase + so, A + ga);
        }
#pragma unroll
        for (int i = 0; i < 4; ++i) {
            int cid = tid + i * 256;             // 0..1023
            int row = cid >> 4;
            int kc  = cid & 15;
            uint32_t so = (uint32_t)(row * TSTR + kc * 4) * 4;
            size_t gb = (size_t)(rowB0 + row) * D_MODEL + c * BK + kc * 4;
            cp16(sbase + TAMAT + so, Wt + gb);
        }
        asm volatile("cp.async.commit_group;" ::: "memory");
    };

    float acc[2][4][4];
#pragma unroll
    for (int mt = 0; mt < 2; ++mt)
#pragma unroll
        for (int nt = 0; nt < 4; ++nt)
#pragma unroll
            for (int i = 0; i < 4; ++i)
                acc[mt][nt][i] = 0.0f;

    const int lmat = lane >> 3;
    const int lrow = lane & 7;
    const int rofs = (lmat & 1) * 8 + lrow;
    const int cofs = (lmat >> 1) * 4;

    issue(0, 0);

    for (int c = 0; c < NCHUNK; ++c) {
        if (c + 1 < NCHUNK) {
            issue(c + 1, (c + 1) & 1);
            asm volatile("cp.async.wait_group 1;" ::: "memory");
        } else {
            asm volatile("cp.async.wait_group 0;" ::: "memory");
        }
        __syncthreads();

        const uint32_t aB = sb + (uint32_t)(c & 1) * TSTAGE;
        const uint32_t bB = aB + TAMAT;

#pragma unroll
        for (int ks = 0; ks < 8; ++ks) {
            const int k0f = ks * 8;
            uint32_t ar[2][4];
#pragma unroll
            for (int mt = 0; mt < 2; ++mt) {
                uint32_t off = (uint32_t)((wm * 32 + mt * 16 + rofs) * TSTR + k0f + cofs) * 4;
                ldsm4(ar[mt], aB + off);
            }
            uint32_t br[2][4];
#pragma unroll
            for (int np = 0; np < 2; ++np) {
                uint32_t off = (uint32_t)((wn * 32 + np * 16 + rofs) * TSTR + k0f + cofs) * 4;
                ldsm4(br[np], bB + off);
            }
#pragma unroll
            for (int mt = 0; mt < 2; ++mt)
#pragma unroll
                for (int nt = 0; nt < 4; ++nt)
                    mma1688_tf32(acc[mt][nt], ar[mt],
                                 br[nt >> 1][nt & 1], br[nt >> 1][2 + (nt & 1)]);
        }
        __syncthreads();
    }

    const int qr = lane >> 2;
    const int qc = (lane & 3) * 2;
#pragma unroll
    for (int mt = 0; mt < 2; ++mt) {
        const int r0 = rowA0 + wm * 32 + mt * 16 + qr;
#pragma unroll
        for (int nt = 0; nt < 4; ++nt) {
            const int col = rowB0 + wn * 32 + nt * 8 + qc;
            const float b0 = bias[col];
            const float b1 = bias[col + 1];
            float2 v0, v1;
            v0.x = acc[mt][nt][0] + b0;  v0.y = acc[mt][nt][1] + b1;
            v1.x = acc[mt][nt][2] + b0;  v1.y = acc[mt][nt][3] + b1;
            *(float2*)&C[(size_t)r0 * D_MODEL + col]       = v0;
            *(float2*)&C[(size_t)(r0 + 8) * D_MODEL + col] = v1;
        }
    }
}

// Fused QKV: grid.x = 48 (3 outputs x 16 N-tiles), grid.y = 64 (M-tiles)
__global__ __launch_bounds__(256, 2)
void gemm_qkv_tf32(const float* __restrict__ A,
                   const float* __restrict__ Wt0,
                   const float* __restrict__ bq, const float* __restrict__ bk,
                   const float* __restrict__ bv,
                   float* __restrict__ qb, float* __restrict__ kb,
                   float* __restrict__ vb)
{
    extern __shared__ __align__(128) char smem[];
    const int which = blockIdx.x >> 4;            // 0=Q 1=K 2=V
    const int rowB0 = (blockIdx.x & 15) * BN;
    const float* Wt = Wt0 + (size_t)which * D_MODEL * D_MODEL;
    const float* bias = (which == 0) ? bq : (which == 1) ? bk : bv;
    float* C = (which == 0) ? qb : (which == 1) ? kb : vb;
    gemm_tf32_body(A, Wt, bias, C, blockIdx.y * BM, rowB0, smem);
}

// Output projection
__global__ __launch_bounds__(256, 2)
void gemm_o_tf32(const float* __restrict__ A,
                 const float* __restrict__ Wt,
                 const float* __restrict__ bias,
                 float* __restrict__ C)
{
    extern __shared__ __align__(128) char smem[];
    gemm_tf32_body(A, Wt, bias, C, blockIdx.y * BM, blockIdx.x * BN, smem);
}

// ---------------------------------------------------------------------------
// Dilated attention: lane = neighbor for scores, lane = dim for V-accum.
// Block = (b, h, 32 queries); K/V/Q window staged in smem.
// Outputs tf32-rounded fp32.
// ---------------------------------------------------------------------------
#define QTILE 32
#define CAP_ROWS 80
#define ASTR 68
#define ATT_SMEM ((2 * CAP_ROWS + QTILE) * ASTR * 4 + 8 * 32 * 4)

__global__ __launch_bounds__(256)
void attn_tile_kernel(const float* __restrict__ Q,
                      const float* __restrict__ Kb,
                      const float* __restrict__ V,
                      float* __restrict__ At,
                      const int* __restrict__ kptr,
                      const int* __restrict__ dptr)
{
    extern __shared__ __align__(16) float sm[];
    float* Ks = sm;
    float* Vs = Ks + CAP_ROWS * ASTR;
    float* Qs = Vs + CAP_ROWS * ASTR;
    float* Ps = Qs + QTILE * ASTR;

    const int tid  = threadIdx.x;
    const int wid  = tid >> 5;
    const int lane = tid & 31;

    const int qt = blockIdx.x & (SEQ / QTILE - 1);
    const int bh = blockIdx.x / (SEQ / QTILE);
    const int h  = bh % NHEADS;
    const int b  = bh / NHEADS;
    const int q0 = qt * QTILE;

    const int kw   = *kptr;
    const int dil  = *dptr;
    const int koff = kw * dil;
    const int tmax = 2 * kw;

    const int base = max(0, q0 - koff);
    const int top  = min(SEQ - 1, q0 + QTILE - 1 + koff);
    const int rows = top - base + 1;
    const bool fast = (rows <= CAP_ROWS) && (tmax <= 31);

    const size_t gbase = (size_t)(b * SEQ) * D_MODEL + h * DHEAD;
    const float scale = rsqrtf((float)DHEAD);

    if (fast) {
        const int nchunk = rows * (DHEAD / 4);
        for (int c = tid; c < nchunk; c += 256) {
            const int r = c >> 4, d4 = (c & 15);
            const size_t g = gbase + (size_t)(base + r) * D_MODEL + d4 * 4;
            *(float4*)&Ks[r * ASTR + d4 * 4] = *(const float4*)&Kb[g];
            *(float4*)&Vs[r * ASTR + d4 * 4] = *(const float4*)&V[g];
        }
        for (int c = tid; c < QTILE * (DHEAD / 4); c += 256) {
            const int r = c >> 4, d4 = (c & 15);
            *(float4*)&Qs[r * ASTR + d4 * 4] =
                *(const float4*)&Q[gbase + (size_t)(q0 + r) * D_MODEL + d4 * 4];
        }
        __syncthreads();

        float* Pw = Ps + wid * 32;

#pragma unroll
        for (int qi = 0; qi < 4; ++qi) {
            const int q = q0 + wid * 4 + qi;
            const int r0q = q - koff - base;

            const int t = lane;
            const int j = q + (t - kw) * dil;
            const bool act = (t <= tmax) && (j >= 0) && (j < SEQ);
            const int rj = min(max(r0q + t * dil, 0), rows - 1);

            float s = 0.0f;
            const float4* krow = (const float4*)&Ks[rj * ASTR];
            const float4* qrow = (const float4*)&Qs[(q - q0) * ASTR];
#pragma unroll
            for (int d4 = 0; d4 < 16; ++d4) {
                float4 kk = krow[d4];
                float4 qq = qrow[d4];
                s += qq.x * kk.x + qq.y * kk.y + qq.z * kk.z + qq.w * kk.w;
            }
            s = act ? s * scale : -1e30f;

            float mx = s;
#pragma unroll
            for (int o = 16; o > 0; o >>= 1)
                mx = fmaxf(mx, __shfl_xor_sync(0xffffffffu, mx, o));
            float e = act ? __expf(s - mx) : 0.0f;
            float sum = e;
#pragma unroll
            for (int o = 16; o > 0; o >>= 1)
                sum += __shfl_xor_sync(0xffffffffu, sum, o);

            Pw[lane] = e;
            __syncwarp();

            float a0 = 0.0f, a1 = 0.0f;
            int rj2 = r0q;
            for (int tt = 0; tt <= tmax; ++tt, rj2 += dil) {
                const float p = Pw[tt];
                const int r = min(max(rj2, 0), rows - 1);
                a0 += p * Vs[r * ASTR + lane];
                a1 += p * Vs[r * ASTR + lane + 32];
            }
            __syncwarp();

            const float inv = 1.0f / sum;
            const size_t rowq = gbase + (size_t)q * D_MODEL;
            At[rowq + lane]      = __uint_as_float(f2tf32(a0 * inv));
            At[rowq + lane + 32] = __uint_as_float(f2tf32(a1 * inv));
        }
        return;
    }

    // fallback: per-neighbor loop straight from gmem (general k/dil)
#pragma unroll
    for (int qi = 0; qi < 4; ++qi) {
        const int q = q0 + wid * 4 + qi;
        const size_t rowq = gbase + (size_t)q * D_MODEL;
        const float q0f = Q[rowq + lane];
        const float q1f = Q[rowq + lane + 32];

        float m = -1e30f, l = 0.0f, a0 = 0.0f, a1 = 0.0f;
        for (int t = 0; t <= tmax; ++t) {
            const int j = q + (t - kw) * dil;
            if (j < 0 || j >= SEQ) continue;
            const size_t rowj = gbase + (size_t)j * D_MODEL;
            float p = q0f * Kb[rowj + lane] + q1f * Kb[rowj + lane + 32];
#pragma unroll
            for (int s = 16; s > 0; s >>= 1)
                p += __shfl_xor_sync(0xffffffffu, p, s);
            const float sc = p * scale;
            const float mn   = fmaxf(m, sc);
            const float corr = __expf(m - mn);
            const float e    = __expf(sc - mn);
            a0 = a0 * corr + e * V[rowj + lane];
            a1 = a1 * corr + e * V[rowj + lane + 32];
            l  = l * corr + e;
            m  = mn;
        }
        const float inv = 1.0f / l;
        At[rowq + lane]      = __uint_as_float(f2tf32(a0 * inv));
        At[rowq + lane + 32] = __uint_as_float(f2tf32(a1 * inv));
    }
}

// ---------------------------------------------------------------------------
// Launch
// ---------------------------------------------------------------------------
extern "C" void kernel_launch(void* const* d_in, const int* in_sizes, int n_in,
                              void* d_out, int out_size)
{
    const float* x  = (const float*)d_in[0];
    const float* Wq = (const float*)d_in[1];
    const float* bq = (const float*)d_in[2];
    const float* Wk = (const float*)d_in[3];
    const float* bk = (const float*)d_in[4];
    const float* Wv = (const float*)d_in[5];
    const float* bv = (const float*)d_in[6];
    const float* Wo = (const float*)d_in[7];
    const float* bo = (const float*)d_in[8];
    const int*   kp = (const int*)d_in[9];
    const int*   dp = (const int*)d_in[10];
    float* out = (float*)d_out;

    void *pq, *pk, *pv, *pxt, *pat, *pwt;
    cudaGetSymbolAddress(&pq,  g_q);
    cudaGetSymbolAddress(&pk,  g_k);
    cudaGetSymbolAddress(&pv,  g_v);
    cudaGetSymbolAddress(&pxt, g_xt);
    cudaGetSymbolAddress(&pat, g_at);
    cudaGetSymbolAddress(&pwt, g_wt);
    float* qbuf = (float*)pq;
    float* kbuf = (float*)pk;
    float* vbuf = (float*)pv;
    float* xt   = (float*)pxt;
    float* at   = (float*)pat;
    float* wt   = (float*)pwt;
    const size_t WSZ = (size_t)D_MODEL * D_MODEL;

    cudaFuncSetAttribute(gemm_qkv_tf32, cudaFuncAttributeMaxDynamicSharedMemorySize, TGEMM_SMEM);
    cudaFuncSetAttribute(gemm_o_tf32,   cudaFuncAttributeMaxDynamicSharedMemorySize, TGEMM_SMEM);
    cudaFuncSetAttribute(attn_tile_kernel, cudaFuncAttributeMaxDynamicSharedMemorySize, ATT_SMEM);

    // 1) x -> tf32-rounded
    {
        int n4 = MROWS * D_MODEL / 4;
        split_kernel<<<(n4 + 255) / 256, 256>>>(x, xt, n4);
    }
    // 2) all 4 weights -> tf32 W^T
    {
        dim3 tb(32, 8), tg(D_MODEL / 32, D_MODEL / 32, 4);
        wsplit_kernel<<<tg, tb>>>(Wq, Wk, Wv, Wo, wt);
    }
    // 3) fused QKV projections (tf32 1-term)
    {
        dim3 gg(3 * (D_MODEL / BN), MROWS / BM);   // (48, 64)
        gemm_qkv_tf32<<<gg, 256, TGEMM_SMEM>>>(xt, wt, bq, bk, bv, qbuf, kbuf, vbuf);
    }
    // 4) dilated attention -> tf32-rounded fp32
    {
        const int n_blocks = BATCH * NHEADS * (SEQ / QTILE);   // 4096
        attn_tile_kernel<<<n_blocks, 256, ATT_SMEM>>>(qbuf, kbuf, vbuf, at, kp, dp);
    }
    // 5) output projection -> d_out
    {
        dim3 gg(D_MODEL / BN, MROWS / BM);         // (16, 64)
        gemm_o_tf32<<<gg, 256, TGEMM_SMEM>>>(at, wt + 3 * WSZ, bo, out);
    }
}

// round 14
// speedup vs baseline: 1.1350x; 1.0022x over previous
#include <cuda_runtime.h>
#include <cuda_bf16.h>
#include <cstdint>
#include <math.h>

// Problem constants
#define D_MODEL 1024
#define NHEADS  16
#define DHEAD   64
#define BATCH   4
#define SEQ     2048
#define MROWS   (BATCH * SEQ)   // 8192

// ---------------------------------------------------------------------------
// Scratch (__device__ globals; no cudaMalloc allowed)
// ---------------------------------------------------------------------------
__device__ float g_q[MROWS * D_MODEL];
__device__ float g_k[MROWS * D_MODEL];
__device__ float g_v[MROWS * D_MODEL];
__device__ float g_xt[MROWS * D_MODEL];        // x tf32-rounded
__device__ float g_at[MROWS * D_MODEL];        // attention out, tf32-rounded
__device__ float g_wt[4][D_MODEL * D_MODEL];   // Wq,Wk,Wv,Wo ^T tf32-rounded

// ---------------------------------------------------------------------------
// PTX helpers (compute_103-safe)
// ---------------------------------------------------------------------------
__device__ __forceinline__ uint32_t smem_u32(const void* p) {
    uint32_t a;
    asm("{ .reg .u64 t; cvta.to.shared.u64 t, %1; cvt.u32.u64 %0, t; }" : "=r"(a) : "l"(p));
    return a;
}
__device__ __forceinline__ void cp16(uint32_t s, const void* g) {
    asm volatile("cp.async.cg.shared.global [%0], [%1], 16;" :: "r"(s), "l"(g));
}
__device__ __forceinline__ void ldsm4(uint32_t* r, uint32_t a) {
    asm volatile("ldmatrix.sync.aligned.m8n8.x4.shared.b16 {%0,%1,%2,%3}, [%4];"
                 : "=r"(r[0]), "=r"(r[1]), "=r"(r[2]), "=r"(r[3]) : "r"(a));
}
__device__ __forceinline__ void mma1688_tf32(float* d, const uint32_t* a, uint32_t b0, uint32_t b1) {
    asm volatile(
        "mma.sync.aligned.m16n8k8.row.col.f32.tf32.tf32.f32 "
        "{%0,%1,%2,%3}, {%4,%5,%6,%7}, {%8,%9}, {%0,%1,%2,%3};"
        : "+f"(d[0]), "+f"(d[1]), "+f"(d[2]), "+f"(d[3])
        : "r"(a[0]), "r"(a[1]), "r"(a[2]), "r"(a[3]), "r"(b0), "r"(b1));
}
__device__ __forceinline__ uint32_t f2tf32(float v) {
    uint32_t u;
    asm("cvt.rna.tf32.f32 %0, %1;" : "=r"(u) : "f"(v));
    return u;
}

// ---------------------------------------------------------------------------
// fp32 -> tf32-rounded fp32, 4 elements/thread
// ---------------------------------------------------------------------------
__global__ __launch_bounds__(256)
void split_kernel(const float* __restrict__ in, float* __restrict__ tf, int n4)
{
    int i = blockIdx.x * blockDim.x + threadIdx.x;
    if (i >= n4) return;
    float4 v = ((const float4*)in)[i];
    uint4 t;
    t.x = f2tf32(v.x); t.y = f2tf32(v.y); t.z = f2tf32(v.z); t.w = f2tf32(v.w);
    ((uint4*)tf)[i] = t;
}

// ---------------------------------------------------------------------------
// W [K,N] fp32 -> W^T [N,K] tf32-rounded; blockIdx.z selects weight
// ---------------------------------------------------------------------------
__global__ __launch_bounds__(256)
void wsplit_kernel(const float* __restrict__ W0, const float* __restrict__ W1,
                   const float* __restrict__ W2, const float* __restrict__ W3,
                   float* __restrict__ wt_base)
{
    __shared__ float t[32][33];
    const int wsel = blockIdx.z;
    const float* W = (wsel == 0) ? W0 : (wsel == 1) ? W1 : (wsel == 2) ? W2 : W3;
    float* wt = wt_base + (size_t)wsel * D_MODEL * D_MODEL;
    const int bx = blockIdx.x * 32;   // col block (N)
    const int by = blockIdx.y * 32;   // row block (K)
    const int x = threadIdx.x, y = threadIdx.y;   // 32 x 8
#pragma unroll
    for (int i = 0; i < 32; i += 8)
        t[y + i][x] = W[(size_t)(by + y + i) * D_MODEL + bx + x];
    __syncthreads();
#pragma unroll
    for (int i = 0; i < 32; i += 8) {
        float v = t[x][y + i];
        size_t o = (size_t)(bx + y + i) * D_MODEL + by + x;
        wt[o] = __uint_as_float(f2tf32(v));
    }
}

// ---------------------------------------------------------------------------
// tf32 1-term GEMM core: C = A[M,K] @ Wt[N,K]^T + bias
// Tile 128x64x64, 256 thr (8 warps 4x2), warp tile 32x32, m16n8k8.
// cp.async double buffer, ONE sync per chunk, stride-68-float smem.
// ---------------------------------------------------------------------------
#define BM 128
#define BN 64
#define BK 64
#define NCHUNK (D_MODEL / BK)           // 16
#define TSTR 68
#define TAMAT (128 * TSTR * 4)          // 34816
#define TBMAT (64 * TSTR * 4)           // 17408
#define TSTAGE (TAMAT + TBMAT)          // 52224
#define TGEMM_SMEM (2 * TSTAGE)         // 104448

__device__ __forceinline__
void gemm_tf32_body(const float* __restrict__ A,
                    const float* __restrict__ Wt,
                    const float* __restrict__ bias,
                    float* __restrict__ C,
                    int rowA0, int rowB0, char* smem)
{
    const uint32_t sb = smem_u32(smem);
    const int tid  = threadIdx.x;
    const int wid  = tid >> 5;
    const int lane = tid & 31;
    const int wm = wid >> 1;          // 0..3
    const int wn = wid & 1;           // 0..1

    auto issue = [&](int c, int s) {
        const uint32_t sbase = sb + (uint32_t)s * TSTAGE;
#pragma unroll
        for (int i = 0; i < 8; ++i) {
            int cid = tid + i * 256;             // 0..2047
            int row = cid >> 4;
            int kc  = cid & 15;
            uint32_t so = (uint32_t)(row * TSTR + kc * 4) * 4;
            size_t ga = (size_t)(rowA0 + row) * D_MODEL + c * BK + kc * 4;
            cp16(sbase + so, A + ga);
        }
#pragma unroll
        for (int i = 0; i < 4; ++i) {
            int cid = tid + i * 256;             // 0..1023
            int row = cid >> 4;
            int kc  = cid & 15;
            uint32_t so = (uint32_t)(row * TSTR + kc * 4) * 4;
            size_t gb = (size_t)(rowB0 + row) * D_MODEL + c * BK + kc * 4;
            cp16(sbase + TAMAT + so, Wt + gb);
        }
        asm volatile("cp.async.commit_group;" ::: "memory");
    };

    float acc[2][4][4];
#pragma unroll
    for (int mt = 0; mt < 2; ++mt)
#pragma unroll
        for (int nt = 0; nt < 4; ++nt)
#pragma unroll
            for (int i = 0; i < 4; ++i)
                acc[mt][nt][i] = 0.0f;

    const int lmat = lane >> 3;
    const int lrow = lane & 7;
    const int rofs = (lmat & 1) * 8 + lrow;
    const int cofs = (lmat >> 1) * 4;

    issue(0, 0);

    for (int c = 0; c < NCHUNK; ++c) {
        // wait for chunk c's data (the only pending group), then one barrier
        // that simultaneously proves: data visible to all, AND every warp is
        // done computing chunk c-1 (compute precedes loop-top sync). Then the
        // prefetch into buffer (c+1)&1 (last computed at c-1) is hazard-free.
        asm volatile("cp.async.wait_group 0;" ::: "memory");
        __syncthreads();
        if (c + 1 < NCHUNK) issue(c + 1, (c + 1) & 1);

        const uint32_t aB = sb + (uint32_t)(c & 1) * TSTAGE;
        const uint32_t bB = aB + TAMAT;

#pragma unroll
        for (int ks = 0; ks < 8; ++ks) {
            const int k0f = ks * 8;
            uint32_t ar[2][4];
#pragma unroll
            for (int mt = 0; mt < 2; ++mt) {
                uint32_t off = (uint32_t)((wm * 32 + mt * 16 + rofs) * TSTR + k0f + cofs) * 4;
                ldsm4(ar[mt], aB + off);
            }
            uint32_t br[2][4];
#pragma unroll
            for (int np = 0; np < 2; ++np) {
                uint32_t off = (uint32_t)((wn * 32 + np * 16 + rofs) * TSTR + k0f + cofs) * 4;
                ldsm4(br[np], bB + off);
            }
#pragma unroll
            for (int mt = 0; mt < 2; ++mt)
#pragma unroll
                for (int nt = 0; nt < 4; ++nt)
                    mma1688_tf32(acc[mt][nt], ar[mt],
                                 br[nt >> 1][nt & 1], br[nt >> 1][2 + (nt & 1)]);
        }
    }

    const int qr = lane >> 2;
    const int qc = (lane & 3) * 2;
#pragma unroll
    for (int mt = 0; mt < 2; ++mt) {
        const int r0 = rowA0 + wm * 32 + mt * 16 + qr;
#pragma unroll
        for (int nt = 0; nt < 4; ++nt) {
            const int col = rowB0 + wn * 32 + nt * 8 + qc;
            const float b0 = bias[col];
            const float b1 = bias[col + 1];
            float2 v0, v1;
            v0.x = acc[mt][nt][0] + b0;  v0.y = acc[mt][nt][1] + b1;
            v1.x = acc[mt][nt][2] + b0;  v1.y = acc[mt][nt][3] + b1;
            *(float2*)&C[(size_t)r0 * D_MODEL + col]       = v0;
            *(float2*)&C[(size_t)(r0 + 8) * D_MODEL + col] = v1;
        }
    }
}

// Fused QKV: grid.x = 48 (3 outputs x 16 N-tiles), grid.y = 64 (M-tiles)
__global__ __launch_bounds__(256, 2)
void gemm_qkv_tf32(const float* __restrict__ A,
                   const float* __restrict__ Wt0,
                   const float* __restrict__ bq, const float* __restrict__ bk,
                   const float* __restrict__ bv,
                   float* __restrict__ qb, float* __restrict__ kb,
                   float* __restrict__ vb)
{
    extern __shared__ __align__(128) char smem[];
    const int which = blockIdx.x >> 4;            // 0=Q 1=K 2=V
    const int rowB0 = (blockIdx.x & 15) * BN;
    const float* Wt = Wt0 + (size_t)which * D_MODEL * D_MODEL;
    const float* bias = (which == 0) ? bq : (which == 1) ? bk : bv;
    float* C = (which == 0) ? qb : (which == 1) ? kb : vb;
    gemm_tf32_body(A, Wt, bias, C, blockIdx.y * BM, rowB0, smem);
}

// Output projection
__global__ __launch_bounds__(256, 2)
void gemm_o_tf32(const float* __restrict__ A,
                 const float* __restrict__ Wt,
                 const float* __restrict__ bias,
                 float* __restrict__ C)
{
    extern __shared__ __align__(128) char smem[];
    gemm_tf32_body(A, Wt, bias, C, blockIdx.y * BM, blockIdx.x * BN, smem);
}

// ---------------------------------------------------------------------------
// Dilated attention v3.
// Phase 1 (lane = neighbor): K stored TRANSPOSED in smem (Kt[d][r], odd row
// stride 81) -> lane stride along r = dil -> worst 2-way bank conflict,
// and inactive lanes skip the dot entirely (act-gated).
// Phase 2 (lane = dim): V row-major, conflict-free.
// ---------------------------------------------------------------------------
#define QTILE 32
#define CAP_ROWS 80
#define ASTR 68                                   // Q/V row stride (floats)
#define KTSTR 81                                  // Kt row stride (floats, odd)
#define ATT_SMEM ((DHEAD * KTSTR + CAP_ROWS * ASTR + QTILE * ASTR + 8 * 32) * 4)

__global__ __launch_bounds__(256)
void attn_tile_kernel(const float* __restrict__ Q,
                      const float* __restrict__ Kb,
                      const float* __restrict__ V,
                      float* __restrict__ At,
                      const int* __restrict__ kptr,
                      const int* __restrict__ dptr)
{
    extern __shared__ __align__(16) float sm[];
    float* Kt = sm;                                // [DHEAD][KTSTR]
    float* Vs = Kt + DHEAD * KTSTR;                // [CAP_ROWS][ASTR]
    float* Qs = Vs + CAP_ROWS * ASTR;              // [QTILE][ASTR]
    float* Ps = Qs + QTILE * ASTR;                 // 8 warps x 32

    const int tid  = threadIdx.x;
    const int wid  = tid >> 5;
    const int lane = tid & 31;

    const int qt = blockIdx.x & (SEQ / QTILE - 1);
    const int bh = blockIdx.x / (SEQ / QTILE);
    const int h  = bh % NHEADS;
    const int b  = bh / NHEADS;
    const int q0 = qt * QTILE;

    const int kw   = *kptr;
    const int dil  = *dptr;
    const int koff = kw * dil;
    const int tmax = 2 * kw;

    const int base = max(0, q0 - koff);
    const int top  = min(SEQ - 1, q0 + QTILE - 1 + koff);
    const int rows = top - base + 1;
    const bool fast = (rows <= CAP_ROWS) && (tmax <= 31);

    const size_t gbase = (size_t)(b * SEQ) * D_MODEL + h * DHEAD;
    const float scale = rsqrtf((float)DHEAD);

    if (fast) {
        // stage: K transposed (scalar scatter, <=2-way STS conflicts),
        //        V row-major, Q row-major
        const int nchunk = rows * (DHEAD / 4);
        for (int c = tid; c < nchunk; c += 256) {
            const int r = c >> 4, d4 = (c & 15);
            const size_t g = gbase + (size_t)(base + r) * D_MODEL + d4 * 4;
            float4 kk = *(const float4*)&Kb[g];
            Kt[(d4 * 4 + 0) * KTSTR + r] = kk.x;
            Kt[(d4 * 4 + 1) * KTSTR + r] = kk.y;
            Kt[(d4 * 4 + 2) * KTSTR + r] = kk.z;
            Kt[(d4 * 4 + 3) * KTSTR + r] = kk.w;
            *(float4*)&Vs[r * ASTR + d4 * 4] = *(const float4*)&V[g];
        }
        for (int c = tid; c < QTILE * (DHEAD / 4); c += 256) {
            const int r = c >> 4, d4 = (c & 15);
            *(float4*)&Qs[r * ASTR + d4 * 4] =
                *(const float4*)&Q[gbase + (size_t)(q0 + r) * D_MODEL + d4 * 4];
        }
        __syncthreads();

        float* Pw = Ps + wid * 32;

#pragma unroll
        for (int qi = 0; qi < 4; ++qi) {
            const int q = q0 + wid * 4 + qi;
            const int r0q = q - koff - base;       // smem row of neighbor t=0

            // ---- phase 1: lane t scores neighbor t (act-gated) ----
            const int t = lane;
            const int j = q + (t - kw) * dil;
            const bool act = (t <= tmax) && (j >= 0) && (j < SEQ);

            float s;
            if (act) {
                const int rj = r0q + t * dil;      // in [0, rows) when act
                const float* qrow = &Qs[(q - q0) * ASTR];
                const float* kcol = &Kt[rj];
                float acc = 0.0f;
#pragma unroll
                for (int d = 0; d < DHEAD; d += 4) {
                    float4 qq = *(const float4*)&qrow[d];   // lane-uniform bcast
                    acc += qq.x * kcol[(d + 0) * KTSTR];
                    acc += qq.y * kcol[(d + 1) * KTSTR];
                    acc += qq.z * kcol[(d + 2) * KTSTR];
                    acc += qq.w * kcol[(d + 3) * KTSTR];
                }
                s = acc * scale;
            } else {
                s = -1e30f;
            }

            float mx = s;
#pragma unroll
            for (int o = 16; o > 0; o >>= 1)
                mx = fmaxf(mx, __shfl_xor_sync(0xffffffffu, mx, o));
            float e = act ? __expf(s - mx) : 0.0f;
            float sum = e;
#pragma unroll
            for (int o = 16; o > 0; o >>= 1)
                sum += __shfl_xor_sync(0xffffffffu, sum, o);

            Pw[lane] = e;
            __syncwarp();

            // ---- phase 2: lane owns dims (lane, lane+32) ----
            float a0 = 0.0f, a1 = 0.0f;
            int rj2 = r0q;
            for (int tt = 0; tt <= tmax; ++tt, rj2 += dil) {
                const float p = Pw[tt];            // 0 for inactive neighbors
                const int r = min(max(rj2, 0), rows - 1);
                a0 += p * Vs[r * ASTR + lane];
                a1 += p * Vs[r * ASTR + lane + 32];
            }
            __syncwarp();

            const float inv = 1.0f / sum;
            const size_t rowq = gbase + (size_t)q * D_MODEL;
            At[rowq + lane]      = __uint_as_float(f2tf32(a0 * inv));
            At[rowq + lane + 32] = __uint_as_float(f2tf32(a1 * inv));
        }
        return;
    }

    // fallback: per-neighbor loop straight from gmem (general k/dil)
#pragma unroll
    for (int qi = 0; qi < 4; ++qi) {
        const int q = q0 + wid * 4 + qi;
        const size_t rowq = gbase + (size_t)q * D_MODEL;
        const float q0f = Q[rowq + lane];
        const float q1f = Q[rowq + lane + 32];

        float m = -1e30f, l = 0.0f, a0 = 0.0f, a1 = 0.0f;
        for (int t = 0; t <= tmax; ++t) {
            const int j = q + (t - kw) * dil;
            if (j < 0 || j >= SEQ) continue;
            const size_t rowj = gbase + (size_t)j * D_MODEL;
            float p = q0f * Kb[rowj + lane] + q1f * Kb[rowj + lane + 32];
#pragma unroll
            for (int s = 16; s > 0; s >>= 1)
                p += __shfl_xor_sync(0xffffffffu, p, s);
            const float sc = p * scale;
            const float mn   = fmaxf(m, sc);
            const float corr = __expf(m - mn);
            const float e    = __expf(sc - mn);
            a0 = a0 * corr + e * V[rowj + lane];
            a1 = a1 * corr + e * V[rowj + lane + 32];
            l  = l * corr + e;
            m  = mn;
        }
        const float inv = 1.0f / l;
        At[rowq + lane]      = __uint_as_float(f2tf32(a0 * inv));
        At[rowq + lane + 32] = __uint_as_float(f2tf32(a1 * inv));
    }
}

// ---------------------------------------------------------------------------
// Launch
// ---------------------------------------------------------------------------
extern "C" void kernel_launch(void* const* d_in, const int* in_sizes, int n_in,
                              void* d_out, int out_size)
{
    const float* x  = (const float*)d_in[0];
    const float* Wq = (const float*)d_in[1];
    const float* bq = (const float*)d_in[2];
    const float* Wk = (const float*)d_in[3];
    const float* bk = (const float*)d_in[4];
    const float* Wv = (const float*)d_in[5];
    const float* bv = (const float*)d_in[6];
    const float* Wo = (const float*)d_in[7];
    const float* bo = (const float*)d_in[8];
    const int*   kp = (const int*)d_in[9];
    const int*   dp = (const int*)d_in[10];
    float* out = (float*)d_out;

    void *pq, *pk, *pv, *pxt, *pat, *pwt;
    cudaGetSymbolAddress(&pq,  g_q);
    cudaGetSymbolAddress(&pk,  g_k);
    cudaGetSymbolAddress(&pv,  g_v);
    cudaGetSymbolAddress(&pxt, g_xt);
    cudaGetSymbolAddress(&pat, g_at);
    cudaGetSymbolAddress(&pwt, g_wt);
    float* qbuf = (float*)pq;
    float* kbuf = (float*)pk;
    float* vbuf = (float*)pv;
    float* xt   = (float*)pxt;
    float* at   = (float*)pat;
    float* wt   = (float*)pwt;
    const size_t WSZ = (size_t)D_MODEL * D_MODEL;

    cudaFuncSetAttribute(gemm_qkv_tf32, cudaFuncAttributeMaxDynamicSharedMemorySize, TGEMM_SMEM);
    cudaFuncSetAttribute(gemm_o_tf32,   cudaFuncAttributeMaxDynamicSharedMemorySize, TGEMM_SMEM);
    cudaFuncSetAttribute(attn_tile_kernel, cudaFuncAttributeMaxDynamicSharedMemorySize, ATT_SMEM);

    // 1) x -> tf32-rounded
    {
        int n4 = MROWS * D_MODEL / 4;
        split_kernel<<<(n4 + 255) / 256, 256>>>(x, xt, n4);
    }
    // 2) all 4 weights -> tf32 W^T
    {
        dim3 tb(32, 8), tg(D_MODEL / 32, D_MODEL / 32, 4);
        wsplit_kernel<<<tg, tb>>>(Wq, Wk, Wv, Wo, wt);
    }
    // 3) fused QKV projections (tf32 1-term)
    {
        dim3 gg(3 * (D_MODEL / BN), MROWS / BM);   // (48, 64)
        gemm_qkv_tf32<<<gg, 256, TGEMM_SMEM>>>(xt, wt, bq, bk, bv, qbuf, kbuf, vbuf);
    }
    // 4) dilated attention -> tf32-rounded fp32
    {
        const int n_blocks = BATCH * NHEADS * (SEQ / QTILE);   // 4096
        attn_tile_kernel<<<n_blocks, 256, ATT_SMEM>>>(qbuf, kbuf, vbuf, at, kp, dp);
    }
    // 5) output projection -> d_out
    {
        dim3 gg(D_MODEL / BN, MROWS / BM);         // (16, 64)
        gemm_o_tf32<<<gg, 256, TGEMM_SMEM>>>(at, wt + 3 * WSZ, bo, out);
    }
}

// round 15
// speedup vs baseline: 1.2085x; 1.0647x over previous
#include <cuda_runtime.h>
#include <cuda_bf16.h>
#include <cstdint>
#include <math.h>

// Problem constants
#define D_MODEL 1024
#define NHEADS  16
#define DHEAD   64
#define BATCH   4
#define SEQ     2048
#define MROWS   (BATCH * SEQ)   // 8192

// ---------------------------------------------------------------------------
// Scratch (__device__ globals; no cudaMalloc allowed)
// ---------------------------------------------------------------------------
__device__ float g_q[MROWS * D_MODEL];
__device__ float g_k[MROWS * D_MODEL];
__device__ float g_v[MROWS * D_MODEL];
__device__ float g_xt[MROWS * D_MODEL];        // x tf32-rounded
__device__ float g_at[MROWS * D_MODEL];        // attention out, tf32-rounded
__device__ float g_wt[4][D_MODEL * D_MODEL];   // Wq,Wk,Wv,Wo ^T tf32-rounded

// ---------------------------------------------------------------------------
// PTX helpers (compute_103-safe)
// ---------------------------------------------------------------------------
__device__ __forceinline__ uint32_t smem_u32(const void* p) {
    uint32_t a;
    asm("{ .reg .u64 t; cvta.to.shared.u64 t, %1; cvt.u32.u64 %0, t; }" : "=r"(a) : "l"(p));
    return a;
}
__device__ __forceinline__ void cp16(uint32_t s, const void* g) {
    asm volatile("cp.async.cg.shared.global [%0], [%1], 16;" :: "r"(s), "l"(g));
}
__device__ __forceinline__ void ldsm4(uint32_t* r, uint32_t a) {
    asm volatile("ldmatrix.sync.aligned.m8n8.x4.shared.b16 {%0,%1,%2,%3}, [%4];"
                 : "=r"(r[0]), "=r"(r[1]), "=r"(r[2]), "=r"(r[3]) : "r"(a));
}
__device__ __forceinline__ void mma1688_tf32(float* d, const uint32_t* a, uint32_t b0, uint32_t b1) {
    asm volatile(
        "mma.sync.aligned.m16n8k8.row.col.f32.tf32.tf32.f32 "
        "{%0,%1,%2,%3}, {%4,%5,%6,%7}, {%8,%9}, {%0,%1,%2,%3};"
        : "+f"(d[0]), "+f"(d[1]), "+f"(d[2]), "+f"(d[3])
        : "r"(a[0]), "r"(a[1]), "r"(a[2]), "r"(a[3]), "r"(b0), "r"(b1));
}
__device__ __forceinline__ uint32_t f2tf32(float v) {
    uint32_t u;
    asm("cvt.rna.tf32.f32 %0, %1;" : "=r"(u) : "f"(v));
    return u;
}
__device__ __forceinline__ float tf32f(float v) { return __uint_as_float(f2tf32(v)); }

// ---------------------------------------------------------------------------
// fp32 -> tf32-rounded fp32, 4 elements/thread
// ---------------------------------------------------------------------------
__global__ __launch_bounds__(256)
void split_kernel(const float* __restrict__ in, float* __restrict__ tf, int n4)
{
    int i = blockIdx.x * blockDim.x + threadIdx.x;
    if (i >= n4) return;
    float4 v = ((const float4*)in)[i];
    uint4 t;
    t.x = f2tf32(v.x); t.y = f2tf32(v.y); t.z = f2tf32(v.z); t.w = f2tf32(v.w);
    ((uint4*)tf)[i] = t;
}

// ---------------------------------------------------------------------------
// W [K,N] fp32 -> W^T [N,K] tf32-rounded; blockIdx.z selects weight
// ---------------------------------------------------------------------------
__global__ __launch_bounds__(256)
void wsplit_kernel(const float* __restrict__ W0, const float* __restrict__ W1,
                   const float* __restrict__ W2, const float* __restrict__ W3,
                   float* __restrict__ wt_base)
{
    __shared__ float t[32][33];
    const int wsel = blockIdx.z;
    const float* W = (wsel == 0) ? W0 : (wsel == 1) ? W1 : (wsel == 2) ? W2 : W3;
    float* wt = wt_base + (size_t)wsel * D_MODEL * D_MODEL;
    const int bx = blockIdx.x * 32;   // col block (N)
    const int by = blockIdx.y * 32;   // row block (K)
    const int x = threadIdx.x, y = threadIdx.y;   // 32 x 8
#pragma unroll
    for (int i = 0; i < 32; i += 8)
        t[y + i][x] = W[(size_t)(by + y + i) * D_MODEL + bx + x];
    __syncthreads();
#pragma unroll
    for (int i = 0; i < 32; i += 8) {
        float v = t[x][y + i];
        size_t o = (size_t)(bx + y + i) * D_MODEL + by + x;
        wt[o] = __uint_as_float(f2tf32(v));
    }
}

// ---------------------------------------------------------------------------
// tf32 1-term GEMM core: C = A[M,K] @ Wt[N,K]^T + bias  (R14-validated)
// ---------------------------------------------------------------------------
#define BM 128
#define BN 64
#define BK 64
#define NCHUNK (D_MODEL / BK)           // 16
#define TSTR 68
#define TAMAT (128 * TSTR * 4)          // 34816
#define TBMAT (64 * TSTR * 4)           // 17408
#define TSTAGE (TAMAT + TBMAT)          // 52224
#define TGEMM_SMEM (2 * TSTAGE)         // 104448

__device__ __forceinline__
void gemm_tf32_body(const float* __restrict__ A,
                    const float* __restrict__ Wt,
                    const float* __restrict__ bias,
                    float* __restrict__ C,
                    int rowA0, int rowB0, char* smem)
{
    const uint32_t sb = smem_u32(smem);
    const int tid  = threadIdx.x;
    const int wid  = tid >> 5;
    const int lane = tid & 31;
    const int wm = wid >> 1;          // 0..3
    const int wn = wid & 1;           // 0..1

    auto issue = [&](int c, int s) {
        const uint32_t sbase = sb + (uint32_t)s * TSTAGE;
#pragma unroll
        for (int i = 0; i < 8; ++i) {
            int cid = tid + i * 256;             // 0..2047
            int row = cid >> 4;
            int kc  = cid & 15;
            uint32_t so = (uint32_t)(row * TSTR + kc * 4) * 4;
            size_t ga = (size_t)(rowA0 + row) * D_MODEL + c * BK + kc * 4;
            cp16(sbase + so, A + ga);
        }
#pragma unroll
        for (int i = 0; i < 4; ++i) {
            int cid = tid + i * 256;             // 0..1023
            int row = cid >> 4;
            int kc  = cid & 15;
            uint32_t so = (uint32_t)(row * TSTR + kc * 4) * 4;
            size_t gb = (size_t)(rowB0 + row) * D_MODEL + c * BK + kc * 4;
            cp16(sbase + TAMAT + so, Wt + gb);
        }
        asm volatile("cp.async.commit_group;" ::: "memory");
    };

    float acc[2][4][4];
#pragma unroll
    for (int mt = 0; mt < 2; ++mt)
#pragma unroll
        for (int nt = 0; nt < 4; ++nt)
#pragma unroll
            for (int i = 0; i < 4; ++i)
                acc[mt][nt][i] = 0.0f;

    const int lmat = lane >> 3;
    const int lrow = lane & 7;
    const int rofs = (lmat & 1) * 8 + lrow;
    const int cofs = (lmat >> 1) * 4;

    issue(0, 0);

    for (int c = 0; c < NCHUNK; ++c) {
        asm volatile("cp.async.wait_group 0;" ::: "memory");
        __syncthreads();
        if (c + 1 < NCHUNK) issue(c + 1, (c + 1) & 1);

        const uint32_t aB = sb + (uint32_t)(c & 1) * TSTAGE;
        const uint32_t bB = aB + TAMAT;

#pragma unroll
        for (int ks = 0; ks < 8; ++ks) {
            const int k0f = ks * 8;
            uint32_t ar[2][4];
#pragma unroll
            for (int mt = 0; mt < 2; ++mt) {
                uint32_t off = (uint32_t)((wm * 32 + mt * 16 + rofs) * TSTR + k0f + cofs) * 4;
                ldsm4(ar[mt], aB + off);
            }
            uint32_t br[2][4];
#pragma unroll
            for (int np = 0; np < 2; ++np) {
                uint32_t off = (uint32_t)((wn * 32 + np * 16 + rofs) * TSTR + k0f + cofs) * 4;
                ldsm4(br[np], bB + off);
            }
#pragma unroll
            for (int mt = 0; mt < 2; ++mt)
#pragma unroll
                for (int nt = 0; nt < 4; ++nt)
                    mma1688_tf32(acc[mt][nt], ar[mt],
                                 br[nt >> 1][nt & 1], br[nt >> 1][2 + (nt & 1)]);
        }
    }

    const int qr = lane >> 2;
    const int qc = (lane & 3) * 2;
#pragma unroll
    for (int mt = 0; mt < 2; ++mt) {
        const int r0 = rowA0 + wm * 32 + mt * 16 + qr;
#pragma unroll
        for (int nt = 0; nt < 4; ++nt) {
            const int col = rowB0 + wn * 32 + nt * 8 + qc;
            const float b0 = bias[col];
            const float b1 = bias[col + 1];
            float2 v0, v1;
            v0.x = acc[mt][nt][0] + b0;  v0.y = acc[mt][nt][1] + b1;
            v1.x = acc[mt][nt][2] + b0;  v1.y = acc[mt][nt][3] + b1;
            *(float2*)&C[(size_t)r0 * D_MODEL + col]       = v0;
            *(float2*)&C[(size_t)(r0 + 8) * D_MODEL + col] = v1;
        }
    }
}

__global__ __launch_bounds__(256, 2)
void gemm_qkv_tf32(const float* __restrict__ A,
                   const float* __restrict__ Wt0,
                   const float* __restrict__ bq, const float* __restrict__ bk,
                   const float* __restrict__ bv,
                   float* __restrict__ qb, float* __restrict__ kb,
                   float* __restrict__ vb)
{
    extern __shared__ __align__(128) char smem[];
    const int which = blockIdx.x >> 4;            // 0=Q 1=K 2=V
    const int rowB0 = (blockIdx.x & 15) * BN;
    const float* Wt = Wt0 + (size_t)which * D_MODEL * D_MODEL;
    const float* bias = (which == 0) ? bq : (which == 1) ? bk : bv;
    float* C = (which == 0) ? qb : (which == 1) ? kb : vb;
    gemm_tf32_body(A, Wt, bias, C, blockIdx.y * BM, rowB0, smem);
}

__global__ __launch_bounds__(256, 2)
void gemm_o_tf32(const float* __restrict__ A,
                 const float* __restrict__ Wt,
                 const float* __restrict__ bias,
                 float* __restrict__ C)
{
    extern __shared__ __align__(128) char smem[];
    gemm_tf32_body(A, Wt, bias, C, blockIdx.y * BM, blockIdx.x * BN, smem);
}

// ---------------------------------------------------------------------------
// Dilated attention v4 — tensor-core formulation.
// Block = (b, h, 32-query tile). Window = dense rows [base, top], rows <= 64.
//   S(32x64) = Qs @ Ks^T   (tf32 mma, same fragment scheme as the GEMM)
//   masked softmax rows of S in smem (mask: r<rows, d%dil==0, |d|<=k*dil)
//   O(32x64) = P @ Vt^T    (Vt staged d-major so it is the B operand)
// Q/K/V/P all rna-rounded to tf32 before the MMAs.
// ---------------------------------------------------------------------------
#define QTILE 32
#define KN 64
#define WSTR 68
#define AMM_SMEM ((QTILE * WSTR + KN * WSTR + KN * WSTR + QTILE * WSTR + QTILE) * 4) // 52352

__global__ __launch_bounds__(256)
void attn_mma_kernel(const float* __restrict__ Q,
                     const float* __restrict__ Kb,
                     const float* __restrict__ V,
                     float* __restrict__ At,
                     const int* __restrict__ kptr,
                     const int* __restrict__ dptr)
{
    extern __shared__ __align__(16) float sm[];
    float* Qs   = sm;                      // [32][WSTR]
    float* Ks   = Qs + QTILE * WSTR;       // [64][WSTR]  (row = window row, col = dim)
    float* Vt   = Ks + KN * WSTR;          // [64][WSTR]  (row = dim, col = window row)
    float* Sc   = Vt + KN * WSTR;          // [32][WSTR]  scores -> P
    float* sums = Sc + QTILE * WSTR;       // [32]

    const int tid  = threadIdx.x;
    const int wid  = tid >> 5;
    const int lane = tid & 31;

    const int qt = blockIdx.x & (SEQ / QTILE - 1);
    const int bh = blockIdx.x / (SEQ / QTILE);
    const int h  = bh % NHEADS;
    const int b  = bh / NHEADS;
    const int q0 = qt * QTILE;

    const int kw   = *kptr;
    const int dil  = *dptr;
    const int koff = kw * dil;

    const int base = max(0, q0 - koff);
    const int top  = min(SEQ - 1, q0 + QTILE - 1 + koff);
    const int rows = top - base + 1;
    const bool fast = (rows <= KN);

    const size_t gbase = (size_t)(b * SEQ) * D_MODEL + h * DHEAD;
    const float scale = rsqrtf((float)DHEAD);

    if (fast) {
        // ---- stage Q (tf32-rna) ----
        for (int c = tid; c < QTILE * 16; c += 256) {
            const int r = c >> 4, d4 = c & 15;
            float4 v = *(const float4*)&Q[gbase + (size_t)(q0 + r) * D_MODEL + d4 * 4];
            uint4 t;
            t.x = f2tf32(v.x); t.y = f2tf32(v.y); t.z = f2tf32(v.z); t.w = f2tf32(v.w);
            *(uint4*)&Qs[r * WSTR + d4 * 4] = t;
        }
        // ---- stage K row-major + V d-major (tf32-rna), zero-pad r >= rows ----
        for (int c = tid; c < KN * 16; c += 256) {
            const int r = c >> 4, d4 = c & 15;
            float4 kk = make_float4(0.f, 0.f, 0.f, 0.f);
            float4 vv = kk;
            if (r < rows) {
                const size_t g = gbase + (size_t)(base + r) * D_MODEL + d4 * 4;
                kk = *(const float4*)&Kb[g];
                vv = *(const float4*)&V[g];
            }
            uint4 tk;
            tk.x = f2tf32(kk.x); tk.y = f2tf32(kk.y); tk.z = f2tf32(kk.z); tk.w = f2tf32(kk.w);
            *(uint4*)&Ks[r * WSTR + d4 * 4] = tk;
            Vt[(d4 * 4 + 0) * WSTR + r] = tf32f(vv.x);
            Vt[(d4 * 4 + 1) * WSTR + r] = tf32f(vv.y);
            Vt[(d4 * 4 + 2) * WSTR + r] = tf32f(vv.z);
            Vt[(d4 * 4 + 3) * WSTR + r] = tf32f(vv.w);
        }
        __syncthreads();

        const int wm = wid >> 2;          // 0..1  (16 q-rows)
        const int wn = wid & 3;           // 0..3  (16 cols)
        const int lmat = lane >> 3;
        const int lrow = lane & 7;
        const int rofs = (lmat & 1) * 8 + lrow;
        const int cofs = (lmat >> 1) * 4;
        const int qr = lane >> 2;
        const int qc = (lane & 3) * 2;

        // ---- S = Qs @ Ks^T ----
        float sa[2][4];
#pragma unroll
        for (int nt = 0; nt < 2; ++nt)
#pragma unroll
            for (int i = 0; i < 4; ++i) sa[nt][i] = 0.0f;
#pragma unroll
        for (int ks = 0; ks < 8; ++ks) {
            const int k0f = ks * 8;
            uint32_t ar[4], br[4];
            ldsm4(ar, smem_u32(&Qs[(wm * 16 + rofs) * WSTR + k0f + cofs]));
            ldsm4(br, smem_u32(&Ks[(wn * 16 + rofs) * WSTR + k0f + cofs]));
            mma1688_tf32(sa[0], ar, br[0], br[2]);
            mma1688_tf32(sa[1], ar, br[1], br[3]);
        }
        // scatter scores to Sc
#pragma unroll
        for (int nt = 0; nt < 2; ++nt) {
            const int r0 = wm * 16 + qr;
            const int col = wn * 16 + nt * 8 + qc;
            *(float2*)&Sc[r0 * WSTR + col]       = make_float2(sa[nt][0], sa[nt][1]);
            *(float2*)&Sc[(r0 + 8) * WSTR + col] = make_float2(sa[nt][2], sa[nt][3]);
        }
        __syncthreads();

        // ---- masked softmax (warp handles rows wid*4 .. wid*4+3) ----
#pragma unroll
        for (int rr = 0; rr < 4; ++rr) {
            const int row = wid * 4 + rr;
            const int q = q0 + row;
            const int c0 = lane, c1 = lane + 32;
            const int dd0 = base + c0 - q;
            const int dd1 = base + c1 - q;
            const bool a0 = (c0 < rows) && (dd0 % dil == 0) && (dd0 >= -koff) && (dd0 <= koff);
            const bool a1 = (c1 < rows) && (dd1 % dil == 0) && (dd1 >= -koff) && (dd1 <= koff);
            float s0 = a0 ? Sc[row * WSTR + c0] * scale : -1e30f;
            float s1 = a1 ? Sc[row * WSTR + c1] * scale : -1e30f;
            float mx = fmaxf(s0, s1);
#pragma unroll
            for (int o = 16; o > 0; o >>= 1)
                mx = fmaxf(mx, __shfl_xor_sync(0xffffffffu, mx, o));
            float e0 = a0 ? tf32f(__expf(s0 - mx)) : 0.0f;
            float e1 = a1 ? tf32f(__expf(s1 - mx)) : 0.0f;
            float sum = e0 + e1;
#pragma unroll
            for (int o = 16; o > 0; o >>= 1)
                sum += __shfl_xor_sync(0xffffffffu, sum, o);
            Sc[row * WSTR + c0] = e0;
            Sc[row * WSTR + c1] = e1;
            if (lane == 0) sums[row] = sum;
        }
        __syncthreads();

        // ---- O = P @ Vt^T ----
        float oa[2][4];
#pragma unroll
        for (int nt = 0; nt < 2; ++nt)
#pragma unroll
            for (int i = 0; i < 4; ++i) oa[nt][i] = 0.0f;
#pragma unroll
        for (int ks = 0; ks < 8; ++ks) {
            const int k0f = ks * 8;
            uint32_t ar[4], br[4];
            ldsm4(ar, smem_u32(&Sc[(wm * 16 + rofs) * WSTR + k0f + cofs]));
            ldsm4(br, smem_u32(&Vt[(wn * 16 + rofs) * WSTR + k0f + cofs]));
            mma1688_tf32(oa[0], ar, br[0], br[2]);
            mma1688_tf32(oa[1], ar, br[1], br[3]);
        }

        // ---- epilogue: normalize, tf32-round, store ----
#pragma unroll
        for (int nt = 0; nt < 2; ++nt) {
            const int rl0 = wm * 16 + qr;
            const int col = wn * 16 + nt * 8 + qc;
            const float inv0 = 1.0f / sums[rl0];
            const float inv1 = 1.0f / sums[rl0 + 8];
            float2 w0, w1;
            w0.x = tf32f(oa[nt][0] * inv0);  w0.y = tf32f(oa[nt][1] * inv0);
            w1.x = tf32f(oa[nt][2] * inv1);  w1.y = tf32f(oa[nt][3] * inv1);
            *(float2*)&At[gbase + (size_t)(q0 + rl0) * D_MODEL + col]     = w0;
            *(float2*)&At[gbase + (size_t)(q0 + rl0 + 8) * D_MODEL + col] = w1;
        }
        return;
    }

    // ---- fallback: per-neighbor loop straight from gmem (general k/dil) ----
    const int tmax = 2 * kw;
#pragma unroll
    for (int qi = 0; qi < 4; ++qi) {
        const int q = q0 + wid * 4 + qi;
        const size_t rowq = gbase + (size_t)q * D_MODEL;
        const float q0f = Q[rowq + lane];
        const float q1f = Q[rowq + lane + 32];

        float m = -1e30f, l = 0.0f, a0 = 0.0f, a1 = 0.0f;
        for (int t = 0; t <= tmax; ++t) {
            const int j = q + (t - kw) * dil;
            if (j < 0 || j >= SEQ) continue;
            const size_t rowj = gbase + (size_t)j * D_MODEL;
            float p = q0f * Kb[rowj + lane] + q1f * Kb[rowj + lane + 32];
#pragma unroll
            for (int s = 16; s > 0; s >>= 1)
                p += __shfl_xor_sync(0xffffffffu, p, s);
            const float sc = p * scale;
            const float mn   = fmaxf(m, sc);
            const float corr = __expf(m - mn);
            const float e    = __expf(sc - mn);
            a0 = a0 * corr + e * V[rowj + lane];
            a1 = a1 * corr + e * V[rowj + lane + 32];
            l  = l * corr + e;
            m  = mn;
        }
        const float inv = 1.0f / l;
        At[rowq + lane]      = __uint_as_float(f2tf32(a0 * inv));
        At[rowq + lane + 32] = __uint_as_float(f2tf32(a1 * inv));
    }
}

// ---------------------------------------------------------------------------
// Launch
// ---------------------------------------------------------------------------
extern "C" void kernel_launch(void* const* d_in, const int* in_sizes, int n_in,
                              void* d_out, int out_size)
{
    const float* x  = (const float*)d_in[0];
    const float* Wq = (const float*)d_in[1];
    const float* bq = (const float*)d_in[2];
    const float* Wk = (const float*)d_in[3];
    const float* bk = (const float*)d_in[4];
    const float* Wv = (const float*)d_in[5];
    const float* bv = (const float*)d_in[6];
    const float* Wo = (const float*)d_in[7];
    const float* bo = (const float*)d_in[8];
    const int*   kp = (const int*)d_in[9];
    const int*   dp = (const int*)d_in[10];
    float* out = (float*)d_out;

    void *pq, *pk, *pv, *pxt, *pat, *pwt;
    cudaGetSymbolAddress(&pq,  g_q);
    cudaGetSymbolAddress(&pk,  g_k);
    cudaGetSymbolAddress(&pv,  g_v);
    cudaGetSymbolAddress(&pxt, g_xt);
    cudaGetSymbolAddress(&pat, g_at);
    cudaGetSymbolAddress(&pwt, g_wt);
    float* qbuf = (float*)pq;
    float* kbuf = (float*)pk;
    float* vbuf = (float*)pv;
    float* xt   = (float*)pxt;
    float* at   = (float*)pat;
    float* wt   = (float*)pwt;
    const size_t WSZ = (size_t)D_MODEL * D_MODEL;

    cudaFuncSetAttribute(gemm_qkv_tf32, cudaFuncAttributeMaxDynamicSharedMemorySize, TGEMM_SMEM);
    cudaFuncSetAttribute(gemm_o_tf32,   cudaFuncAttributeMaxDynamicSharedMemorySize, TGEMM_SMEM);
    cudaFuncSetAttribute(attn_mma_kernel, cudaFuncAttributeMaxDynamicSharedMemorySize, AMM_SMEM);

    // 1) x -> tf32-rounded
    {
        int n4 = MROWS * D_MODEL / 4;
        split_kernel<<<(n4 + 255) / 256, 256>>>(x, xt, n4);
    }
    // 2) all 4 weights -> tf32 W^T
    {
        dim3 tb(32, 8), tg(D_MODEL / 32, D_MODEL / 32, 4);
        wsplit_kernel<<<tg, tb>>>(Wq, Wk, Wv, Wo, wt);
    }
    // 3) fused QKV projections (tf32 1-term)
    {
        dim3 gg(3 * (D_MODEL / BN), MROWS / BM);   // (48, 64)
        gemm_qkv_tf32<<<gg, 256, TGEMM_SMEM>>>(xt, wt, bq, bk, bv, qbuf, kbuf, vbuf);
    }
    // 4) dilated attention (tensor cores) -> tf32-rounded fp32
    {
        const int n_blocks = BATCH * NHEADS * (SEQ / QTILE);   // 4096
        attn_mma_kernel<<<n_blocks, 256, AMM_SMEM>>>(qbuf, kbuf, vbuf, at, kp, dp);
    }
    // 5) output projection -> d_out
    {
        dim3 gg(D_MODEL / BN, MROWS / BM);         // (16, 64)
        gemm_o_tf32<<<gg, 256, TGEMM_SMEM>>>(at, wt + 3 * WSZ, bo, out);
    }
}

// round 16
// speedup vs baseline: 1.2346x; 1.0216x over previous
#include <cuda_runtime.h>
#include <cuda_bf16.h>
#include <cstdint>
#include <math.h>

// Problem constants
#define D_MODEL 1024
#define NHEADS  16
#define DHEAD   64
#define BATCH   4
#define SEQ     2048
#define MROWS   (BATCH * SEQ)   // 8192

// ---------------------------------------------------------------------------
// Scratch (__device__ globals; no cudaMalloc allowed)
// ---------------------------------------------------------------------------
__device__ float g_q[MROWS * D_MODEL];
__device__ float g_k[MROWS * D_MODEL];
__device__ float g_v[MROWS * D_MODEL];
__device__ float g_xt[MROWS * D_MODEL];        // x tf32-rounded
__device__ float g_at[MROWS * D_MODEL];        // attention out, tf32-rounded
__device__ float g_wt[4][D_MODEL * D_MODEL];   // Wq,Wk,Wv,Wo ^T tf32-rounded

// ---------------------------------------------------------------------------
// PTX helpers (compute_103-safe)
// ---------------------------------------------------------------------------
__device__ __forceinline__ uint32_t smem_u32(const void* p) {
    uint32_t a;
    asm("{ .reg .u64 t; cvta.to.shared.u64 t, %1; cvt.u32.u64 %0, t; }" : "=r"(a) : "l"(p));
    return a;
}
__device__ __forceinline__ void cp16(uint32_t s, const void* g) {
    asm volatile("cp.async.cg.shared.global [%0], [%1], 16;" :: "r"(s), "l"(g));
}
__device__ __forceinline__ void ldsm4(uint32_t* r, uint32_t a) {
    asm volatile("ldmatrix.sync.aligned.m8n8.x4.shared.b16 {%0,%1,%2,%3}, [%4];"
                 : "=r"(r[0]), "=r"(r[1]), "=r"(r[2]), "=r"(r[3]) : "r"(a));
}
__device__ __forceinline__ void mma1688_tf32(float* d, const uint32_t* a, uint32_t b0, uint32_t b1) {
    asm volatile(
        "mma.sync.aligned.m16n8k8.row.col.f32.tf32.tf32.f32 "
        "{%0,%1,%2,%3}, {%4,%5,%6,%7}, {%8,%9}, {%0,%1,%2,%3};"
        : "+f"(d[0]), "+f"(d[1]), "+f"(d[2]), "+f"(d[3])
        : "r"(a[0]), "r"(a[1]), "r"(a[2]), "r"(a[3]), "r"(b0), "r"(b1));
}
__device__ __forceinline__ uint32_t f2tf32(float v) {
    uint32_t u;
    asm("cvt.rna.tf32.f32 %0, %1;" : "=r"(u) : "f"(v));
    return u;
}
__device__ __forceinline__ float tf32f(float v) { return __uint_as_float(f2tf32(v)); }

// ---------------------------------------------------------------------------
// fp32 -> tf32-rounded fp32, 4 elements/thread
// ---------------------------------------------------------------------------
__global__ __launch_bounds__(256)
void split_kernel(const float* __restrict__ in, float* __restrict__ tf, int n4)
{
    int i = blockIdx.x * blockDim.x + threadIdx.x;
    if (i >= n4) return;
    float4 v = ((const float4*)in)[i];
    uint4 t;
    t.x = f2tf32(v.x); t.y = f2tf32(v.y); t.z = f2tf32(v.z); t.w = f2tf32(v.w);
    ((uint4*)tf)[i] = t;
}

// ---------------------------------------------------------------------------
// W [K,N] fp32 -> W^T [N,K] tf32-rounded; blockIdx.z selects weight
// ---------------------------------------------------------------------------
__global__ __launch_bounds__(256)
void wsplit_kernel(const float* __restrict__ W0, const float* __restrict__ W1,
                   const float* __restrict__ W2, const float* __restrict__ W3,
                   float* __restrict__ wt_base)
{
    __shared__ float t[32][33];
    const int wsel = blockIdx.z;
    const float* W = (wsel == 0) ? W0 : (wsel == 1) ? W1 : (wsel == 2) ? W2 : W3;
    float* wt = wt_base + (size_t)wsel * D_MODEL * D_MODEL;
    const int bx = blockIdx.x * 32;   // col block (N)
    const int by = blockIdx.y * 32;   // row block (K)
    const int x = threadIdx.x, y = threadIdx.y;   // 32 x 8
#pragma unroll
    for (int i = 0; i < 32; i += 8)
        t[y + i][x] = W[(size_t)(by + y + i) * D_MODEL + bx + x];
    __syncthreads();
#pragma unroll
    for (int i = 0; i < 32; i += 8) {
        float v = t[x][y + i];
        size_t o = (size_t)(bx + y + i) * D_MODEL + by + x;
        wt[o] = __uint_as_float(f2tf32(v));
    }
}

// ---------------------------------------------------------------------------
// tf32 1-term GEMM core: C = A[M,K] @ Wt[N,K]^T + bias  (R14-validated)
// ---------------------------------------------------------------------------
#define BM 128
#define BN 64
#define BK 64
#define NCHUNK (D_MODEL / BK)           // 16
#define TSTR 68
#define TAMAT (128 * TSTR * 4)          // 34816
#define TBMAT (64 * TSTR * 4)           // 17408
#define TSTAGE (TAMAT + TBMAT)          // 52224
#define TGEMM_SMEM (2 * TSTAGE)         // 104448

__device__ __forceinline__
void gemm_tf32_body(const float* __restrict__ A,
                    const float* __restrict__ Wt,
                    const float* __restrict__ bias,
                    float* __restrict__ C,
                    int rowA0, int rowB0, char* smem)
{
    const uint32_t sb = smem_u32(smem);
    const int tid  = threadIdx.x;
    const int wid  = tid >> 5;
    const int lane = tid & 31;
    const int wm = wid >> 1;          // 0..3
    const int wn = wid & 1;           // 0..1

    auto issue = [&](int c, int s) {
        const uint32_t sbase = sb + (uint32_t)s * TSTAGE;
#pragma unroll
        for (int i = 0; i < 8; ++i) {
            int cid = tid + i * 256;             // 0..2047
            int row = cid >> 4;
            int kc  = cid & 15;
            uint32_t so = (uint32_t)(row * TSTR + kc * 4) * 4;
            size_t ga = (size_t)(rowA0 + row) * D_MODEL + c * BK + kc * 4;
            cp16(sbase + so, A + ga);
        }
#pragma unroll
        for (int i = 0; i < 4; ++i) {
            int cid = tid + i * 256;             // 0..1023
            int row = cid >> 4;
            int kc  = cid & 15;
            uint32_t so = (uint32_t)(row * TSTR + kc * 4) * 4;
            size_t gb = (size_t)(rowB0 + row) * D_MODEL + c * BK + kc * 4;
            cp16(sbase + TAMAT + so, Wt + gb);
        }
        asm volatile("cp.async.commit_group;" ::: "memory");
    };

    float acc[2][4][4];
#pragma unroll
    for (int mt = 0; mt < 2; ++mt)
#pragma unroll
        for (int nt = 0; nt < 4; ++nt)
#pragma unroll
            for (int i = 0; i < 4; ++i)
                acc[mt][nt][i] = 0.0f;

    const int lmat = lane >> 3;
    const int lrow = lane & 7;
    const int rofs = (lmat & 1) * 8 + lrow;
    const int cofs = (lmat >> 1) * 4;

    issue(0, 0);

    for (int c = 0; c < NCHUNK; ++c) {
        asm volatile("cp.async.wait_group 0;" ::: "memory");
        __syncthreads();
        if (c + 1 < NCHUNK) issue(c + 1, (c + 1) & 1);

        const uint32_t aB = sb + (uint32_t)(c & 1) * TSTAGE;
        const uint32_t bB = aB + TAMAT;

#pragma unroll
        for (int ks = 0; ks < 8; ++ks) {
            const int k0f = ks * 8;
            uint32_t ar[2][4];
#pragma unroll
            for (int mt = 0; mt < 2; ++mt) {
                uint32_t off = (uint32_t)((wm * 32 + mt * 16 + rofs) * TSTR + k0f + cofs) * 4;
                ldsm4(ar[mt], aB + off);
            }
            uint32_t br[2][4];
#pragma unroll
            for (int np = 0; np < 2; ++np) {
                uint32_t off = (uint32_t)((wn * 32 + np * 16 + rofs) * TSTR + k0f + cofs) * 4;
                ldsm4(br[np], bB + off);
            }
#pragma unroll
            for (int mt = 0; mt < 2; ++mt)
#pragma unroll
                for (int nt = 0; nt < 4; ++nt)
                    mma1688_tf32(acc[mt][nt], ar[mt],
                                 br[nt >> 1][nt & 1], br[nt >> 1][2 + (nt & 1)]);
        }
    }

    const int qr = lane >> 2;
    const int qc = (lane & 3) * 2;
#pragma unroll
    for (int mt = 0; mt < 2; ++mt) {
        const int r0 = rowA0 + wm * 32 + mt * 16 + qr;
#pragma unroll
        for (int nt = 0; nt < 4; ++nt) {
            const int col = rowB0 + wn * 32 + nt * 8 + qc;
            const float b0 = bias[col];
            const float b1 = bias[col + 1];
            float2 v0, v1;
            v0.x = acc[mt][nt][0] + b0;  v0.y = acc[mt][nt][1] + b1;
            v1.x = acc[mt][nt][2] + b0;  v1.y = acc[mt][nt][3] + b1;
            *(float2*)&C[(size_t)r0 * D_MODEL + col]       = v0;
            *(float2*)&C[(size_t)(r0 + 8) * D_MODEL + col] = v1;
        }
    }
}

__global__ __launch_bounds__(256, 2)
void gemm_qkv_tf32(const float* __restrict__ A,
                   const float* __restrict__ Wt0,
                   const float* __restrict__ bq, const float* __restrict__ bk,
                   const float* __restrict__ bv,
                   float* __restrict__ qb, float* __restrict__ kb,
                   float* __restrict__ vb)
{
    extern __shared__ __align__(128) char smem[];
    const int which = blockIdx.x >> 4;            // 0=Q 1=K 2=V
    const int rowB0 = (blockIdx.x & 15) * BN;
    const float* Wt = Wt0 + (size_t)which * D_MODEL * D_MODEL;
    const float* bias = (which == 0) ? bq : (which == 1) ? bk : bv;
    float* C = (which == 0) ? qb : (which == 1) ? kb : vb;
    gemm_tf32_body(A, Wt, bias, C, blockIdx.y * BM, rowB0, smem);
}

__global__ __launch_bounds__(256, 2)
void gemm_o_tf32(const float* __restrict__ A,
                 const float* __restrict__ Wt,
                 const float* __restrict__ bias,
                 float* __restrict__ C)
{
    extern __shared__ __align__(128) char smem[];
    gemm_tf32_body(A, Wt, bias, C, blockIdx.y * BM, blockIdx.x * BN, smem);
}

// ---------------------------------------------------------------------------
// Dilated attention v5 — tensor-core, no V transpose.
//   S(32x64) = Qs @ Ks^T        (tf32 mma, ldsm fragments)
//   masked softmax (cheap modulo: 3 runtime divisions per thread total)
//   O(32x64) = P @ V            (B fragment via 2 direct LDS.32 from
//                                row-major Vs, stride 72 -> conflict-free)
// ---------------------------------------------------------------------------
#define QTILE 32
#define KN 64
#define WSTR 68                                   // Qs/Ks/Sc row stride
#define VSTR 72                                   // Vs row stride (frag-load conflict-free)
#define AMM_SMEM ((QTILE * WSTR + KN * WSTR + KN * VSTR + QTILE * WSTR + QTILE) * 4)

__global__ __launch_bounds__(256)
void attn_mma_kernel(const float* __restrict__ Q,
                     const float* __restrict__ Kb,
                     const float* __restrict__ V,
                     float* __restrict__ At,
                     const int* __restrict__ kptr,
                     const int* __restrict__ dptr)
{
    extern __shared__ __align__(16) float sm[];
    float* Qs   = sm;                      // [32][WSTR]
    float* Ks   = Qs + QTILE * WSTR;       // [64][WSTR]  (row = window row, col = dim)
    float* Vs   = Ks + KN * WSTR;          // [64][VSTR]  (row = window row, col = dim)
    float* Sc   = Vs + KN * VSTR;          // [32][WSTR]  scores -> P
    float* sums = Sc + QTILE * WSTR;       // [32]

    const int tid  = threadIdx.x;
    const int wid  = tid >> 5;
    const int lane = tid & 31;

    const int qt = blockIdx.x & (SEQ / QTILE - 1);
    const int bh = blockIdx.x / (SEQ / QTILE);
    const int h  = bh % NHEADS;
    const int b  = bh / NHEADS;
    const int q0 = qt * QTILE;

    const int kw   = *kptr;
    const int dil  = *dptr;
    const int koff = kw * dil;

    const int base = max(0, q0 - koff);
    const int top  = min(SEQ - 1, q0 + QTILE - 1 + koff);
    const int rows = top - base + 1;
    const bool fast = (rows <= KN);

    const size_t gbase = (size_t)(b * SEQ) * D_MODEL + h * DHEAD;
    const float scale = rsqrtf((float)DHEAD);

    if (fast) {
        // ---- stage Q (tf32-rna) ----
        for (int c = tid; c < QTILE * 16; c += 256) {
            const int r = c >> 4, d4 = c & 15;
            float4 v = *(const float4*)&Q[gbase + (size_t)(q0 + r) * D_MODEL + d4 * 4];
            uint4 t;
            t.x = f2tf32(v.x); t.y = f2tf32(v.y); t.z = f2tf32(v.z); t.w = f2tf32(v.w);
            *(uint4*)&Qs[r * WSTR + d4 * 4] = t;
        }
        // ---- stage K + V row-major (tf32-rna), zero-pad r >= rows ----
        for (int c = tid; c < KN * 16; c += 256) {
            const int r = c >> 4, d4 = c & 15;
            float4 kk = make_float4(0.f, 0.f, 0.f, 0.f);
            float4 vv = kk;
            if (r < rows) {
                const size_t g = gbase + (size_t)(base + r) * D_MODEL + d4 * 4;
                kk = *(const float4*)&Kb[g];
                vv = *(const float4*)&V[g];
            }
            uint4 tk, tv;
            tk.x = f2tf32(kk.x); tk.y = f2tf32(kk.y); tk.z = f2tf32(kk.z); tk.w = f2tf32(kk.w);
            tv.x = f2tf32(vv.x); tv.y = f2tf32(vv.y); tv.z = f2tf32(vv.z); tv.w = f2tf32(vv.w);
            *(uint4*)&Ks[r * WSTR + d4 * 4] = tk;
            *(uint4*)&Vs[r * VSTR + d4 * 4] = tv;
        }
        __syncthreads();

        const int wm = wid >> 2;          // 0..1  (16 q-rows)
        const int wn = wid & 3;           // 0..3  (16 cols)
        const int lmat = lane >> 3;
        const int lrow = lane & 7;
        const int rofs = (lmat & 1) * 8 + lrow;
        const int cofs = (lmat >> 1) * 4;
        const int qr = lane >> 2;
        const int qc = (lane & 3) * 2;

        // ---- S = Qs @ Ks^T ----
        float sa[2][4];
#pragma unroll
        for (int nt = 0; nt < 2; ++nt)
#pragma unroll
            for (int i = 0; i < 4; ++i) sa[nt][i] = 0.0f;
#pragma unroll
        for (int ks = 0; ks < 8; ++ks) {
            const int k0f = ks * 8;
            uint32_t ar[4], br[4];
            ldsm4(ar, smem_u32(&Qs[(wm * 16 + rofs) * WSTR + k0f + cofs]));
            ldsm4(br, smem_u32(&Ks[(wn * 16 + rofs) * WSTR + k0f + cofs]));
            mma1688_tf32(sa[0], ar, br[0], br[2]);
            mma1688_tf32(sa[1], ar, br[1], br[3]);
        }
        // scatter scores to Sc
#pragma unroll
        for (int nt = 0; nt < 2; ++nt) {
            const int r0 = wm * 16 + qr;
            const int col = wn * 16 + nt * 8 + qc;
            *(float2*)&Sc[r0 * WSTR + col]       = make_float2(sa[nt][0], sa[nt][1]);
            *(float2*)&Sc[(r0 + 8) * WSTR + col] = make_float2(sa[nt][2], sa[nt][3]);
        }
        __syncthreads();

        // ---- masked softmax; modulo via 3 divisions total ----
        const int c0 = lane, c1 = lane + 32;
        const int m0 = c0 % dil;
        const int m1 = c1 % dil;
        int rm = (q0 + wid * 4 - base) % dil;     // r0q % dil for first row
#pragma unroll
        for (int rr = 0; rr < 4; ++rr) {
            const int row = wid * 4 + rr;
            const int r0q = q0 + row - base;      // q - base >= 0
            const bool a0 = (c0 < rows) && (m0 == rm) && (c0 >= r0q - koff) && (c0 <= r0q + koff);
            const bool a1 = (c1 < rows) && (m1 == rm) && (c1 >= r0q - koff) && (c1 <= r0q + koff);
            float s0 = a0 ? Sc[row * WSTR + c0] * scale : -1e30f;
            float s1 = a1 ? Sc[row * WSTR + c1] * scale : -1e30f;
            float mx = fmaxf(s0, s1);
#pragma unroll
            for (int o = 16; o > 0; o >>= 1)
                mx = fmaxf(mx, __shfl_xor_sync(0xffffffffu, mx, o));
            float e0 = a0 ? tf32f(__expf(s0 - mx)) : 0.0f;
            float e1 = a1 ? tf32f(__expf(s1 - mx)) : 0.0f;
            float sum = e0 + e1;
#pragma unroll
            for (int o = 16; o > 0; o >>= 1)
                sum += __shfl_xor_sync(0xffffffffu, sum, o);
            Sc[row * WSTR + c0] = e0;
            Sc[row * WSTR + c1] = e1;
            if (lane == 0) sums[row] = sum;
            rm = (rm + 1 == dil) ? 0 : rm + 1;
        }
        __syncthreads();

        // ---- O = P @ V  (B fragment direct from row-major Vs) ----
        // m16n8k8 B frag: lane l -> col n = l>>2; b0 = B[k=l&3][n], b1 = B[k+4][n]
        const int bn = lane >> 2;                 // 0..7 col within octet
        const int bk = lane & 3;                  // k within half
        float oa[2][4];
#pragma unroll
        for (int nt = 0; nt < 2; ++nt)
#pragma unroll
            for (int i = 0; i < 4; ++i) oa[nt][i] = 0.0f;
#pragma unroll
        for (int ks = 0; ks < 8; ++ks) {
            const int k0f = ks * 8;
            uint32_t ar[4];
            ldsm4(ar, smem_u32(&Sc[(wm * 16 + rofs) * WSTR + k0f + cofs]));
            const float* vb0 = &Vs[(k0f + bk) * VSTR + wn * 16 + bn];
#pragma unroll
            for (int nt = 0; nt < 2; ++nt) {
                const uint32_t b0 = __float_as_uint(vb0[nt * 8]);
                const uint32_t b1 = __float_as_uint(vb0[4 * VSTR + nt * 8]);
                mma1688_tf32(oa[nt], ar, b0, b1);
            }
        }

        // ---- epilogue: normalize, tf32-round, store ----
#pragma unroll
        for (int nt = 0; nt < 2; ++nt) {
            const int rl0 = wm * 16 + qr;
            const int col = wn * 16 + nt * 8 + qc;
            const float inv0 = 1.0f / sums[rl0];
            const float inv1 = 1.0f / sums[rl0 + 8];
            float2 w0, w1;
            w0.x = tf32f(oa[nt][0] * inv0);  w0.y = tf32f(oa[nt][1] * inv0);
            w1.x = tf32f(oa[nt][2] * inv1);  w1.y = tf32f(oa[nt][3] * inv1);
            *(float2*)&At[gbase + (size_t)(q0 + rl0) * D_MODEL + col]     = w0;
            *(float2*)&At[gbase + (size_t)(q0 + rl0 + 8) * D_MODEL + col] = w1;
        }
        return;
    }

    // ---- fallback: per-neighbor loop straight from gmem (general k/dil) ----
    const int tmax = 2 * kw;
#pragma unroll
    for (int qi = 0; qi < 4; ++qi) {
        const int q = q0 + wid * 4 + qi;
        const size_t rowq = gbase + (size_t)q * D_MODEL;
        const float q0f = Q[rowq + lane];
        const float q1f = Q[rowq + lane + 32];

        float m = -1e30f, l = 0.0f, a0 = 0.0f, a1 = 0.0f;
        for (int t = 0; t <= tmax; ++t) {
            const int j = q + (t - kw) * dil;
            if (j < 0 || j >= SEQ) continue;
            const size_t rowj = gbase + (size_t)j * D_MODEL;
            float p = q0f * Kb[rowj + lane] + q1f * Kb[rowj + lane + 32];
#pragma unroll
            for (int s = 16; s > 0; s >>= 1)
                p += __shfl_xor_sync(0xffffffffu, p, s);
            const float sc = p * scale;
            const float mn   = fmaxf(m, sc);
            const float corr = __expf(m - mn);
            const float e    = __expf(sc - mn);
            a0 = a0 * corr + e * V[rowj + lane];
            a1 = a1 * corr + e * V[rowj + lane + 32];
            l  = l * corr + e;
            m  = mn;
        }
        const float inv = 1.0f / l;
        At[rowq + lane]      = __uint_as_float(f2tf32(a0 * inv));
        At[rowq + lane + 32] = __uint_as_float(f2tf32(a1 * inv));
    }
}

// ---------------------------------------------------------------------------
// Launch
// ---------------------------------------------------------------------------
extern "C" void kernel_launch(void* const* d_in, const int* in_sizes, int n_in,
                              void* d_out, int out_size)
{
    const float* x  = (const float*)d_in[0];
    const float* Wq = (const float*)d_in[1];
    const float* bq = (const float*)d_in[2];
    const float* Wk = (const float*)d_in[3];
    const float* bk = (const float*)d_in[4];
    const float* Wv = (const float*)d_in[5];
    const float* bv = (const float*)d_in[6];
    const float* Wo = (const float*)d_in[7];
    const float* bo = (const float*)d_in[8];
    const int*   kp = (const int*)d_in[9];
    const int*   dp = (const int*)d_in[10];
    float* out = (float*)d_out;

    void *pq, *pk, *pv, *pxt, *pat, *pwt;
    cudaGetSymbolAddress(&pq,  g_q);
    cudaGetSymbolAddress(&pk,  g_k);
    cudaGetSymbolAddress(&pv,  g_v);
    cudaGetSymbolAddress(&pxt, g_xt);
    cudaGetSymbolAddress(&pat, g_at);
    cudaGetSymbolAddress(&pwt, g_wt);
    float* qbuf = (float*)pq;
    float* kbuf = (float*)pk;
    float* vbuf = (float*)pv;
    float* xt   = (float*)pxt;
    float* at   = (float*)pat;
    float* wt   = (float*)pwt;
    const size_t WSZ = (size_t)D_MODEL * D_MODEL;

    cudaFuncSetAttribute(gemm_qkv_tf32, cudaFuncAttributeMaxDynamicSharedMemorySize, TGEMM_SMEM);
    cudaFuncSetAttribute(gemm_o_tf32,   cudaFuncAttributeMaxDynamicSharedMemorySize, TGEMM_SMEM);
    cudaFuncSetAttribute(attn_mma_kernel, cudaFuncAttributeMaxDynamicSharedMemorySize, AMM_SMEM);

    // 1) x -> tf32-rounded
    {
        int n4 = MROWS * D_MODEL / 4;
        split_kernel<<<(n4 + 255) / 256, 256>>>(x, xt, n4);
    }
    // 2) all 4 weights -> tf32 W^T
    {
        dim3 tb(32, 8), tg(D_MODEL / 32, D_MODEL / 32, 4);
        wsplit_kernel<<<tg, tb>>>(Wq, Wk, Wv, Wo, wt);
    }
    // 3) fused QKV projections (tf32 1-term)
    {
        dim3 gg(3 * (D_MODEL / BN), MROWS / BM);   // (48, 64)
        gemm_qkv_tf32<<<gg, 256, TGEMM_SMEM>>>(xt, wt, bq, bk, bv, qbuf, kbuf, vbuf);
    }
    // 4) dilated attention (tensor cores) -> tf32-rounded fp32
    {
        const int n_blocks = BATCH * NHEADS * (SEQ / QTILE);   // 4096
        attn_mma_kernel<<<n_blocks, 256, AMM_SMEM>>>(qbuf, kbuf, vbuf, at, kp, dp);
    }
    // 5) output projection -> d_out
    {
        dim3 gg(D_MODEL / BN, MROWS / BM);         // (16, 64)
        gemm_o_tf32<<<gg, 256, TGEMM_SMEM>>>(at, wt + 3 * WSZ, bo, out);
    }
}

// round 17
// speedup vs baseline: 2.3795x; 1.9273x over previous
#include <cuda_runtime.h>
#include <cuda_fp16.h>
#include <cstdint>
#include <math.h>

// Problem constants
#define D_MODEL 1024
#define NHEADS  16
#define DHEAD   64
#define BATCH   4
#define SEQ     2048
#define MROWS   (BATCH * SEQ)   // 8192

// ---------------------------------------------------------------------------
// Scratch (__device__ globals; no cudaMalloc allowed)
// ---------------------------------------------------------------------------
__device__ float g_q[MROWS * D_MODEL];
__device__ float g_k[MROWS * D_MODEL];
__device__ float g_v[MROWS * D_MODEL];
__device__ __half g_xh[MROWS * D_MODEL];        // x fp16
__device__ __half g_ah[MROWS * D_MODEL];        // attention out fp16
__device__ __half g_wh[4][D_MODEL * D_MODEL];   // Wq,Wk,Wv,Wo ^T fp16

// ---------------------------------------------------------------------------
// PTX helpers (compute_103-safe)
// ---------------------------------------------------------------------------
__device__ __forceinline__ uint32_t smem_u32(const void* p) {
    uint32_t a;
    asm("{ .reg .u64 t; cvta.to.shared.u64 t, %1; cvt.u32.u64 %0, t; }" : "=r"(a) : "l"(p));
    return a;
}
__device__ __forceinline__ void cp16(uint32_t s, const void* g) {
    asm volatile("cp.async.cg.shared.global [%0], [%1], 16;" :: "r"(s), "l"(g));
}
__device__ __forceinline__ void ldsm4(uint32_t* r, uint32_t a) {
    asm volatile("ldmatrix.sync.aligned.m8n8.x4.shared.b16 {%0,%1,%2,%3}, [%4];"
                 : "=r"(r[0]), "=r"(r[1]), "=r"(r[2]), "=r"(r[3]) : "r"(a));
}
// fp16 k16 MMA, fp32 accum
__device__ __forceinline__ void mma16816h(float* d, const uint32_t* a, const uint32_t* b) {
    asm volatile(
        "mma.sync.aligned.m16n8k16.row.col.f32.f16.f16.f32 "
        "{%0,%1,%2,%3}, {%4,%5,%6,%7}, {%8,%9}, {%0,%1,%2,%3};"
        : "+f"(d[0]), "+f"(d[1]), "+f"(d[2]), "+f"(d[3])
        : "r"(a[0]), "r"(a[1]), "r"(a[2]), "r"(a[3]), "r"(b[0]), "r"(b[1]));
}
// tf32 k8 MMA (attention only)
__device__ __forceinline__ void mma1688_tf32(float* d, const uint32_t* a, uint32_t b0, uint32_t b1) {
    asm volatile(
        "mma.sync.aligned.m16n8k8.row.col.f32.tf32.tf32.f32 "
        "{%0,%1,%2,%3}, {%4,%5,%6,%7}, {%8,%9}, {%0,%1,%2,%3};"
        : "+f"(d[0]), "+f"(d[1]), "+f"(d[2]), "+f"(d[3])
        : "r"(a[0]), "r"(a[1]), "r"(a[2]), "r"(a[3]), "r"(b0), "r"(b1));
}
__device__ __forceinline__ uint32_t f2tf32(float v) {
    uint32_t u;
    asm("cvt.rna.tf32.f32 %0, %1;" : "=r"(u) : "f"(v));
    return u;
}
__device__ __forceinline__ float tf32f(float v) { return __uint_as_float(f2tf32(v)); }

// ---------------------------------------------------------------------------
// fp32 -> fp16, 4 elements/thread
// ---------------------------------------------------------------------------
__global__ __launch_bounds__(256)
void split_kernel(const float* __restrict__ in, __half* __restrict__ hh, int n4)
{
    int i = blockIdx.x * blockDim.x + threadIdx.x;
    if (i >= n4) return;
    float4 v = ((const float4*)in)[i];
    __half2 h0 = __floats2half2_rn(v.x, v.y);
    __half2 h1 = __floats2half2_rn(v.z, v.w);
    ((__half2*)hh)[2 * i]     = h0;
    ((__half2*)hh)[2 * i + 1] = h1;
}

// ---------------------------------------------------------------------------
// W [K,N] fp32 -> W^T [N,K] fp16; blockIdx.z selects weight
// ---------------------------------------------------------------------------
__global__ __launch_bounds__(256)
void wsplit_kernel(const float* __restrict__ W0, const float* __restrict__ W1,
                   const float* __restrict__ W2, const float* __restrict__ W3,
                   __half* __restrict__ wh_base)
{
    __shared__ float t[32][33];
    const int wsel = blockIdx.z;
    const float* W = (wsel == 0) ? W0 : (wsel == 1) ? W1 : (wsel == 2) ? W2 : W3;
    __half* wh = wh_base + (size_t)wsel * D_MODEL * D_MODEL;
    const int bx = blockIdx.x * 32;   // col block (N)
    const int by = blockIdx.y * 32;   // row block (K)
    const int x = threadIdx.x, y = threadIdx.y;   // 32 x 8
#pragma unroll
    for (int i = 0; i < 32; i += 8)
        t[y + i][x] = W[(size_t)(by + y + i) * D_MODEL + bx + x];
    __syncthreads();
#pragma unroll
    for (int i = 0; i < 32; i += 8) {
        float v = t[x][y + i];
        size_t o = (size_t)(bx + y + i) * D_MODEL + by + x;
        wh[o] = __float2half_rn(v);
    }
}

// ---------------------------------------------------------------------------
// fp16 1-term GEMM core: C = A[M,K] @ Wt[N,K]^T + bias
// Tile 128x64x64, 256 thr (8 warps 4x2), warp tile 32x32, m16n8k16 fp16.
// cp.async double buffer, ONE sync per chunk, stride-72-half smem.
// Fragment addressing identical to the R8-validated bf16 kernel.
// ---------------------------------------------------------------------------
#define BM 128
#define BN 64
#define BK 64
#define NCHUNK (D_MODEL / BK)           // 16
#define HSTR 72
#define HAMAT (128 * HSTR * 2)          // 18432
#define HBMAT (64 * HSTR * 2)           // 9216
#define HSTAGE (HAMAT + HBMAT)          // 27648
#define HGEMM_SMEM (2 * HSTAGE)         // 55296

__device__ __forceinline__
void gemm_fp16_body(const __half* __restrict__ A,
                    const __half* __restrict__ Wt,
                    const float* __restrict__ bias,
                    float* __restrict__ C,
                    int rowA0, int rowB0, char* smem)
{
    const uint32_t sb = smem_u32(smem);
    const int tid  = threadIdx.x;
    const int wid  = tid >> 5;
    const int lane = tid & 31;
    const int wm = wid >> 1;          // 0..3 (32 rows each)
    const int wn = wid & 1;           // 0..1 (32 cols each)

    auto issue = [&](int c, int s) {
        const uint32_t sbase = sb + (uint32_t)s * HSTAGE;
#pragma unroll
        for (int i = 0; i < 4; ++i) {
            int cid = tid + i * 256;          // 0..1023
            int row = cid >> 3;
            int kc  = cid & 7;
            uint32_t so = (uint32_t)(row * HSTR + kc * 8) * 2;
            size_t ga = (size_t)(rowA0 + row) * D_MODEL + c * BK + kc * 8;
            cp16(sbase + so, A + ga);
        }
#pragma unroll
        for (int i = 0; i < 2; ++i) {
            int cid = tid + i * 256;          // 0..511
            int row = cid >> 3;
            int kc  = cid & 7;
            uint32_t so = (uint32_t)(row * HSTR + kc * 8) * 2;
            size_t gb = (size_t)(rowB0 + row) * D_MODEL + c * BK + kc * 8;
            cp16(sbase + HAMAT + so, Wt + gb);
        }
        asm volatile("cp.async.commit_group;" ::: "memory");
    };

    float acc[2][4][4];
#pragma unroll
    for (int mt = 0; mt < 2; ++mt)
#pragma unroll
        for (int nt = 0; nt < 4; ++nt)
#pragma unroll
            for (int i = 0; i < 4; ++i)
                acc[mt][nt][i] = 0.0f;

    const int arow = lane & 15;
    const int acol = (lane >> 4) * 8;
    const int brow = (lane & 7) + ((lane >> 4) << 3);
    const int bcol = ((lane >> 3) & 1) * 8;

    issue(0, 0);

    for (int c = 0; c < NCHUNK; ++c) {
        asm volatile("cp.async.wait_group 0;" ::: "memory");
        __syncthreads();
        if (c + 1 < NCHUNK) issue(c + 1, (c + 1) & 1);

        const uint32_t aB = sb + (uint32_t)(c & 1) * HSTAGE;
        const uint32_t bB = aB + HAMAT;

#pragma unroll
        for (int ks = 0; ks < 4; ++ks) {
            const int k0 = ks * 16;
            uint32_t ah[2][4];
#pragma unroll
            for (int mt = 0; mt < 2; ++mt) {
                uint32_t off = (uint32_t)((wm * 32 + mt * 16 + arow) * HSTR + k0 + acol) * 2;
                ldsm4(ah[mt], aB + off);
            }
            uint32_t bh[2][4];
#pragma unroll
            for (int bt = 0; bt < 2; ++bt) {
                uint32_t off = (uint32_t)((wn * 32 + bt * 16 + brow) * HSTR + k0 + bcol) * 2;
                ldsm4(bh[bt], bB + off);
            }
#pragma unroll
            for (int mt = 0; mt < 2; ++mt)
#pragma unroll
                for (int nt = 0; nt < 4; ++nt)
                    mma16816h(acc[mt][nt], ah[mt], &bh[nt >> 1][(nt & 1) * 2]);
        }
    }

    const int qr = lane >> 2;
    const int qc = (lane & 3) * 2;
#pragma unroll
    for (int mt = 0; mt < 2; ++mt) {
        const int r0 = rowA0 + wm * 32 + mt * 16 + qr;
#pragma unroll
        for (int nt = 0; nt < 4; ++nt) {
            const int col = rowB0 + wn * 32 + nt * 8 + qc;
            const float b0 = bias[col];
            const float b1 = bias[col + 1];
            float2 v0, v1;
            v0.x = acc[mt][nt][0] + b0;  v0.y = acc[mt][nt][1] + b1;
            v1.x = acc[mt][nt][2] + b0;  v1.y = acc[mt][nt][3] + b1;
            *(float2*)&C[(size_t)r0 * D_MODEL + col]       = v0;
            *(float2*)&C[(size_t)(r0 + 8) * D_MODEL + col] = v1;
        }
    }
}

// Fused QKV: grid.x = 48 (3 outputs x 16 N-tiles), grid.y = 64 (M-tiles)
__global__ __launch_bounds__(256, 3)
void gemm_qkv_fp16(const __half* __restrict__ A,
                   const __half* __restrict__ Wh0,
                   const float* __restrict__ bq, const float* __restrict__ bk,
                   const float* __restrict__ bv,
                   float* __restrict__ qb, float* __restrict__ kb,
                   float* __restrict__ vb)
{
    extern __shared__ __align__(128) char smem[];
    const int which = blockIdx.x >> 4;            // 0=Q 1=K 2=V
    const int rowB0 = (blockIdx.x & 15) * BN;
    const __half* Wt = Wh0 + (size_t)which * D_MODEL * D_MODEL;
    const float* bias = (which == 0) ? bq : (which == 1) ? bk : bv;
    float* C = (which == 0) ? qb : (which == 1) ? kb : vb;
    gemm_fp16_body(A, Wt, bias, C, blockIdx.y * BM, rowB0, smem);
}

// Output projection
__global__ __launch_bounds__(256, 3)
void gemm_o_fp16(const __half* __restrict__ A,
                 const __half* __restrict__ Wt,
                 const float* __restrict__ bias,
                 float* __restrict__ C)
{
    extern __shared__ __align__(128) char smem[];
    gemm_fp16_body(A, Wt, bias, C, blockIdx.y * BM, blockIdx.x * BN, smem);
}

// ---------------------------------------------------------------------------
// Dilated attention (R16-validated tf32 MMA form); epilogue emits fp16.
// ---------------------------------------------------------------------------
#define QTILE 32
#define KN 64
#define WSTR 68                                   // Qs/Ks/Sc row stride
#define VSTR 72                                   // Vs row stride
#define AMM_SMEM ((QTILE * WSTR + KN * WSTR + KN * VSTR + QTILE * WSTR + QTILE) * 4)

__global__ __launch_bounds__(256)
void attn_mma_kernel(const float* __restrict__ Q,
                     const float* __restrict__ Kb,
                     const float* __restrict__ V,
                     __half* __restrict__ At,
                     const int* __restrict__ kptr,
                     const int* __restrict__ dptr)
{
    extern __shared__ __align__(16) float sm[];
    float* Qs   = sm;                      // [32][WSTR]
    float* Ks   = Qs + QTILE * WSTR;       // [64][WSTR]
    float* Vs   = Ks + KN * WSTR;          // [64][VSTR]
    float* Sc   = Vs + KN * VSTR;          // [32][WSTR]
    float* sums = Sc + QTILE * WSTR;       // [32]

    const int tid  = threadIdx.x;
    const int wid  = tid >> 5;
    const int lane = tid & 31;

    const int qt = blockIdx.x & (SEQ / QTILE - 1);
    const int bh = blockIdx.x / (SEQ / QTILE);
    const int h  = bh % NHEADS;
    const int b  = bh / NHEADS;
    const int q0 = qt * QTILE;

    const int kw   = *kptr;
    const int dil  = *dptr;
    const int koff = kw * dil;

    const int base = max(0, q0 - koff);
    const int top  = min(SEQ - 1, q0 + QTILE - 1 + koff);
    const int rows = top - base + 1;
    const bool fast = (rows <= KN);

    const size_t gbase = (size_t)(b * SEQ) * D_MODEL + h * DHEAD;
    const float scale = rsqrtf((float)DHEAD);

    if (fast) {
        // ---- stage Q (tf32-rna) ----
        for (int c = tid; c < QTILE * 16; c += 256) {
            const int r = c >> 4, d4 = c & 15;
            float4 v = *(const float4*)&Q[gbase + (size_t)(q0 + r) * D_MODEL + d4 * 4];
            uint4 t;
            t.x = f2tf32(v.x); t.y = f2tf32(v.y); t.z = f2tf32(v.z); t.w = f2tf32(v.w);
            *(uint4*)&Qs[r * WSTR + d4 * 4] = t;
        }
        // ---- stage K + V row-major (tf32-rna), zero-pad r >= rows ----
        for (int c = tid; c < KN * 16; c += 256) {
            const int r = c >> 4, d4 = c & 15;
            float4 kk = make_float4(0.f, 0.f, 0.f, 0.f);
            float4 vv = kk;
            if (r < rows) {
                const size_t g = gbase + (size_t)(base + r) * D_MODEL + d4 * 4;
                kk = *(const float4*)&Kb[g];
                vv = *(const float4*)&V[g];
            }
            uint4 tk, tv;
            tk.x = f2tf32(kk.x); tk.y = f2tf32(kk.y); tk.z = f2tf32(kk.z); tk.w = f2tf32(kk.w);
            tv.x = f2tf32(vv.x); tv.y = f2tf32(vv.y); tv.z = f2tf32(vv.z); tv.w = f2tf32(vv.w);
            *(uint4*)&Ks[r * WSTR + d4 * 4] = tk;
            *(uint4*)&Vs[r * VSTR + d4 * 4] = tv;
        }
        __syncthreads();

        const int wm = wid >> 2;          // 0..1
        const int wn = wid & 3;           // 0..3
        const int lmat = lane >> 3;
        const int lrow = lane & 7;
        const int rofs = (lmat & 1) * 8 + lrow;
        const int cofs = (lmat >> 1) * 4;
        const int qr = lane >> 2;
        const int qc = (lane & 3) * 2;

        // ---- S = Qs @ Ks^T ----
        float sa[2][4];
#pragma unroll
        for (int nt = 0; nt < 2; ++nt)
#pragma unroll
            for (int i = 0; i < 4; ++i) sa[nt][i] = 0.0f;
#pragma unroll
        for (int ks = 0; ks < 8; ++ks) {
            const int k0f = ks * 8;
            uint32_t ar[4], br[4];
            ldsm4(ar, smem_u32(&Qs[(wm * 16 + rofs) * WSTR + k0f + cofs]));
            ldsm4(br, smem_u32(&Ks[(wn * 16 + rofs) * WSTR + k0f + cofs]));
            mma1688_tf32(sa[0], ar, br[0], br[2]);
            mma1688_tf32(sa[1], ar, br[1], br[3]);
        }
#pragma unroll
        for (int nt = 0; nt < 2; ++nt) {
            const int r0 = wm * 16 + qr;
            const int col = wn * 16 + nt * 8 + qc;
            *(float2*)&Sc[r0 * WSTR + col]       = make_float2(sa[nt][0], sa[nt][1]);
            *(float2*)&Sc[(r0 + 8) * WSTR + col] = make_float2(sa[nt][2], sa[nt][3]);
        }
        __syncthreads();

        // ---- masked softmax ----
        const int c0 = lane, c1 = lane + 32;
        const int m0 = c0 % dil;
        const int m1 = c1 % dil;
        int rm = (q0 + wid * 4 - base) % dil;
#pragma unroll
        for (int rr = 0; rr < 4; ++rr) {
            const int row = wid * 4 + rr;
            const int r0q = q0 + row - base;
            const bool a0 = (c0 < rows) && (m0 == rm) && (c0 >= r0q - koff) && (c0 <= r0q + koff);
            const bool a1 = (c1 < rows) && (m1 == rm) && (c1 >= r0q - koff) && (c1 <= r0q + koff);
            float s0 = a0 ? Sc[row * WSTR + c0] * scale : -1e30f;
            float s1 = a1 ? Sc[row * WSTR + c1] * scale : -1e30f;
            float mx = fmaxf(s0, s1);
#pragma unroll
            for (int o = 16; o > 0; o >>= 1)
                mx = fmaxf(mx, __shfl_xor_sync(0xffffffffu, mx, o));
            float e0 = a0 ? tf32f(__expf(s0 - mx)) : 0.0f;
            float e1 = a1 ? tf32f(__expf(s1 - mx)) : 0.0f;
            float sum = e0 + e1;
#pragma unroll
            for (int o = 16; o > 0; o >>= 1)
                sum += __shfl_xor_sync(0xffffffffu, sum, o);
            Sc[row * WSTR + c0] = e0;
            Sc[row * WSTR + c1] = e1;
            if (lane == 0) sums[row] = sum;
            rm = (rm + 1 == dil) ? 0 : rm + 1;
        }
        __syncthreads();

        // ---- O = P @ V (B fragment direct from row-major Vs) ----
        const int bn = lane >> 2;
        const int bk = lane & 3;
        float oa[2][4];
#pragma unroll
        for (int nt = 0; nt < 2; ++nt)
#pragma unroll
            for (int i = 0; i < 4; ++i) oa[nt][i] = 0.0f;
#pragma unroll
        for (int ks = 0; ks < 8; ++ks) {
            const int k0f = ks * 8;
            uint32_t ar[4];
            ldsm4(ar, smem_u32(&Sc[(wm * 16 + rofs) * WSTR + k0f + cofs]));
            const float* vb0 = &Vs[(k0f + bk) * VSTR + wn * 16 + bn];
#pragma unroll
            for (int nt = 0; nt < 2; ++nt) {
                const uint32_t b0 = __float_as_uint(vb0[nt * 8]);
                const uint32_t b1 = __float_as_uint(vb0[4 * VSTR + nt * 8]);
                mma1688_tf32(oa[nt], ar, b0, b1);
            }
        }

        // ---- epilogue: normalize, fp16 store ----
#pragma unroll
        for (int nt = 0; nt < 2; ++nt) {
            const int rl0 = wm * 16 + qr;
            const int col = wn * 16 + nt * 8 + qc;
            const float inv0 = 1.0f / sums[rl0];
            const float inv1 = 1.0f / sums[rl0 + 8];
            __half2 w0 = __floats2half2_rn(oa[nt][0] * inv0, oa[nt][1] * inv0);
            __half2 w1 = __floats2half2_rn(oa[nt][2] * inv1, oa[nt][3] * inv1);
            *(__half2*)&At[gbase + (size_t)(q0 + rl0) * D_MODEL + col]     = w0;
            *(__half2*)&At[gbase + (size_t)(q0 + rl0 + 8) * D_MODEL + col] = w1;
        }
        return;
    }

    // ---- fallback: per-neighbor loop straight from gmem (general k/dil) ----
    const int tmax = 2 * kw;
#pragma unroll
    for (int qi = 0; qi < 4; ++qi) {
        const int q = q0 + wid * 4 + qi;
        const size_t rowq = gbase + (size_t)q * D_MODEL;
        const float q0f = Q[rowq + lane];
        const float q1f = Q[rowq + lane + 32];

        float m = -1e30f, l = 0.0f, a0 = 0.0f, a1 = 0.0f;
        for (int t = 0; t <= tmax; ++t) {
            const int j = q + (t - kw) * dil;
            if (j < 0 || j >= SEQ) continue;
            const size_t rowj = gbase + (size_t)j * D_MODEL;
            float p = q0f * Kb[rowj + lane] + q1f * Kb[rowj + lane + 32];
#pragma unroll
            for (int s = 16; s > 0; s >>= 1)
                p += __shfl_xor_sync(0xffffffffu, p, s);
            const float sc = p * scale;
            const float mn   = fmaxf(m, sc);
            const float corr = __expf(m - mn);
            const float e    = __expf(sc - mn);
            a0 = a0 * corr + e * V[rowj + lane];
            a1 = a1 * corr + e * V[rowj + lane + 32];
            l  = l * corr + e;
            m  = mn;
        }
        const float inv = 1.0f / l;
        At[rowq + lane]      = __float2half_rn(a0 * inv);
        At[rowq + lane + 32] = __float2half_rn(a1 * inv);
    }
}

// ---------------------------------------------------------------------------
// Launch
// ---------------------------------------------------------------------------
extern "C" void kernel_launch(void* const* d_in, const int* in_sizes, int n_in,
                              void* d_out, int out_size)
{
    const float* x  = (const float*)d_in[0];
    const float* Wq = (const float*)d_in[1];
    const float* bq = (const float*)d_in[2];
    const float* Wk = (const float*)d_in[3];
    const float* bk = (const float*)d_in[4];
    const float* Wv = (const float*)d_in[5];
    const float* bv = (const float*)d_in[6];
    const float* Wo = (const float*)d_in[7];
    const float* bo = (const float*)d_in[8];
    const int*   kp = (const int*)d_in[9];
    const int*   dp = (const int*)d_in[10];
    float* out = (float*)d_out;

    void *pq, *pk, *pv, *pxh, *pah, *pwh;
    cudaGetSymbolAddress(&pq,  g_q);
    cudaGetSymbolAddress(&pk,  g_k);
    cudaGetSymbolAddress(&pv,  g_v);
    cudaGetSymbolAddress(&pxh, g_xh);
    cudaGetSymbolAddress(&pah, g_ah);
    cudaGetSymbolAddress(&pwh, g_wh);
    float* qbuf = (float*)pq;
    float* kbuf = (float*)pk;
    float* vbuf = (float*)pv;
    __half* xh = (__half*)pxh;
    __half* ah = (__half*)pah;
    __half* wh = (__half*)pwh;
    const size_t WSZ = (size_t)D_MODEL * D_MODEL;

    cudaFuncSetAttribute(gemm_qkv_fp16, cudaFuncAttributeMaxDynamicSharedMemorySize, HGEMM_SMEM);
    cudaFuncSetAttribute(gemm_o_fp16,   cudaFuncAttributeMaxDynamicSharedMemorySize, HGEMM_SMEM);
    cudaFuncSetAttribute(attn_mma_kernel, cudaFuncAttributeMaxDynamicSharedMemorySize, AMM_SMEM);

    // 1) x -> fp16
    {
        int n4 = MROWS * D_MODEL / 4;
        split_kernel<<<(n4 + 255) / 256, 256>>>(x, xh, n4);
    }
    // 2) all 4 weights -> fp16 W^T
    {
        dim3 tb(32, 8), tg(D_MODEL / 32, D_MODEL / 32, 4);
        wsplit_kernel<<<tg, tb>>>(Wq, Wk, Wv, Wo, wh);
    }
    // 3) fused QKV projections (fp16 1-term)
    {
        dim3 gg(3 * (D_MODEL / BN), MROWS / BM);   // (48, 64)
        gemm_qkv_fp16<<<gg, 256, HGEMM_SMEM>>>(xh, wh, bq, bk, bv, qbuf, kbuf, vbuf);
    }
    // 4) dilated attention (tf32 tensor cores) -> fp16
    {
        const int n_blocks = BATCH * NHEADS * (SEQ / QTILE);   // 4096
        attn_mma_kernel<<<n_blocks, 256, AMM_SMEM>>>(qbuf, kbuf, vbuf, ah, kp, dp);
    }
    // 5) output projection -> d_out
    {
        dim3 gg(D_MODEL / BN, MROWS / BM);         // (16, 64)
        gemm_o_fp16<<<gg, 256, HGEMM_SMEM>>>(ah, wh + 3 * WSZ, bo, out);
    }
}